// round 2
// baseline (speedup 1.0000x reference)
#include <cuda_runtime.h>
#include <math.h>

#define NN 10000
#define E0 80000
#define EE 90000
#define F0 512
#define F1 4096
#define F2 1024
#define F3 7
#define NSLOPE 0.2f
#define ENC_NEG_INF 0x807FFFFF

// -------- scratch (static device globals; no allocation) --------
__device__ float g_agg1[(size_t)NN * F0];   // attention-weighted agg of x   (20.5 MB)
__device__ float g_h1[(size_t)NN * F1];     // relu(agg1@W1 + b1)            (164 MB)
__device__ float g_h2[(size_t)NN * F2];     // h1@W2 (pre-agg, pre-bias)     (41 MB)
__device__ float g_agg2[(size_t)NN * F2];   // agg of h2, then relu(.+b2)    (41 MB)
__device__ float g_h3[NN * F3];
__device__ float g_agg3[NN * F3];
__device__ float g_ssrc[NN], g_sdst[NN];
__device__ int   g_emax[NN];
__device__ float g_denom[NN];
__device__ float g_ex[EE];
__device__ float g_v1s[F0], g_v1d[F0];

// -------- helpers --------
__device__ __forceinline__ int f2oi(float f) {
    int i = __float_as_int(f);
    return (i >= 0) ? i : (i ^ 0x7FFFFFFF);
}
__device__ __forceinline__ float oi2f(int i) {
    return (i >= 0) ? __int_as_float(i) : __int_as_float(i ^ 0x7FFFFFFF);
}
__device__ __forceinline__ void edge_sd(const int* __restrict__ ei, int e, int& s, int& d) {
    if (e < E0) { s = ei[e]; d = ei[E0 + e]; }
    else        { s = e - E0; d = e - E0; }
}

// -------- init: zero agg buffer + reset per-node max/denom --------
__global__ void k_init(float* __restrict__ agg, long n) {
    long i0 = (long)blockIdx.x * blockDim.x + threadIdx.x;
    long stride = (long)gridDim.x * blockDim.x;
    for (long i = i0; i < n; i += stride) agg[i] = 0.0f;
    if (i0 < NN) { g_emax[i0] = ENC_NEG_INF; g_denom[i0] = 0.0f; }
}

// -------- v = W1 @ a  (projected attention vectors, layer 1) --------
__global__ void k_v1(const float* __restrict__ W1, const float* __restrict__ as,
                     const float* __restrict__ ad) {
    int r = blockIdx.x;            // 0..511
    int tid = threadIdx.x;         // 256
    float ss = 0.f, sd = 0.f;
    const float* wrow = W1 + (size_t)r * F1;
    for (int j = tid; j < F1; j += 256) {
        float w = wrow[j];
        ss += w * as[j];
        sd += w * ad[j];
    }
    __shared__ float s1[256], s2[256];
    s1[tid] = ss; s2[tid] = sd;
    __syncthreads();
    for (int s = 128; s > 0; s >>= 1) {
        if (tid < s) { s1[tid] += s1[tid + s]; s2[tid] += s2[tid + s]; }
        __syncthreads();
    }
    if (tid == 0) { g_v1s[r] = s1[0]; g_v1d[r] = s2[0]; }
}

// -------- per-node attention scores: s_src[i]=X[i].vs, s_dst[i]=X[i].vd --------
__global__ void k_scores(const float* __restrict__ X, const float* __restrict__ vs,
                         const float* __restrict__ vd, int F) {
    int node = blockIdx.x;
    int tid = threadIdx.x;         // 128
    const float* xr = X + (size_t)node * F;
    float ss = 0.f, sd = 0.f;
    for (int j = tid; j < F; j += 128) {
        float x = xr[j];
        ss += x * vs[j];
        sd += x * vd[j];
    }
    __shared__ float s1[128], s2[128];
    s1[tid] = ss; s2[tid] = sd;
    __syncthreads();
    for (int s = 64; s > 0; s >>= 1) {
        if (tid < s) { s1[tid] += s1[tid + s]; s2[tid] += s2[tid + s]; }
        __syncthreads();
    }
    if (tid == 0) { g_ssrc[node] = s1[0]; g_sdst[node] = s2[0]; }
}

// -------- edge pass 1: segment max of leaky_relu logits --------
__global__ void k_edge_max(const int* __restrict__ ei) {
    int e = blockIdx.x * blockDim.x + threadIdx.x;
    if (e >= EE) return;
    int s, d; edge_sd(ei, e, s, d);
    float v = g_ssrc[s] + g_sdst[d];
    v = (v > 0.f) ? v : NSLOPE * v;
    atomicMax(&g_emax[d], f2oi(v));
}

// -------- edge pass 2: exp + segment sum --------
__global__ void k_edge_exp(const int* __restrict__ ei) {
    int e = blockIdx.x * blockDim.x + threadIdx.x;
    if (e >= EE) return;
    int s, d; edge_sd(ei, e, s, d);
    float v = g_ssrc[s] + g_sdst[d];
    v = (v > 0.f) ? v : NSLOPE * v;
    float ex = __expf(v - oi2f(g_emax[d]));
    g_ex[e] = ex;
    atomicAdd(&g_denom[d], ex);
}

// -------- aggregation kernels (alpha fused as ex/denom) --------
__global__ void k_agg1(const float* __restrict__ x, const int* __restrict__ ei) {
    int e = blockIdx.x;
    int s, d; edge_sd(ei, e, s, d);
    float w = g_ex[e] / g_denom[d];
    float4 xv = ((const float4*)(x + (size_t)s * F0))[threadIdx.x];  // 128 thr * 4 = 512
    float* o = g_agg1 + (size_t)d * F0 + threadIdx.x * 4;
    atomicAdd(o + 0, w * xv.x);
    atomicAdd(o + 1, w * xv.y);
    atomicAdd(o + 2, w * xv.z);
    atomicAdd(o + 3, w * xv.w);
}

__global__ void k_agg2(const int* __restrict__ ei) {
    int e = blockIdx.x;
    int s, d; edge_sd(ei, e, s, d);
    float w = g_ex[e] / g_denom[d];
    float4 hv = ((const float4*)(g_h2 + (size_t)s * F2))[threadIdx.x]; // 256 thr * 4 = 1024
    float* o = g_agg2 + (size_t)d * F2 + threadIdx.x * 4;
    atomicAdd(o + 0, w * hv.x);
    atomicAdd(o + 1, w * hv.y);
    atomicAdd(o + 2, w * hv.z);
    atomicAdd(o + 3, w * hv.w);
}

__global__ void k_agg3(const int* __restrict__ ei) {
    int e = blockIdx.x * blockDim.x + threadIdx.x;
    if (e >= EE) return;
    int s, d; edge_sd(ei, e, s, d);
    float w = g_ex[e] / g_denom[d];
    #pragma unroll
    for (int j = 0; j < F3; j++)
        atomicAdd(&g_agg3[d * F3 + j], w * g_h3[s * F3 + j]);
}

// -------- bias + relu in place on g_agg2 --------
__global__ void k_bias_relu2(const float* __restrict__ b2) {
    long i0 = (long)blockIdx.x * blockDim.x + threadIdx.x;
    long stride = (long)gridDim.x * blockDim.x;
    long n = (long)NN * F2;
    for (long i = i0; i < n; i += stride) {
        float v = g_agg2[i] + b2[i % F2];
        g_agg2[i] = (v > 0.f) ? v : 0.f;
    }
}

// -------- SGEMM: C[M,Nc] = A[M,K]@B[K,Nc] (+bias, relu). BM=BN=128, BK=8 --------
__global__ void __launch_bounds__(256, 2)
sgemm(const float* __restrict__ A, const float* __restrict__ B, float* __restrict__ C,
      int M, int Nc, int K, const float* __restrict__ bias, int doRelu) {
    __shared__ float As[8 * 128];
    __shared__ float Bs[8 * 128];
    int tid = threadIdx.x;
    int brow = blockIdx.y, bcol = blockIdx.x;
    int aRow = tid >> 1, aCol = (tid & 1) * 4;
    int bRow = tid >> 5, bCol = (tid & 31) * 4;
    int gARow = brow * 128 + aRow;
    int tr = (tid >> 4) << 3;
    int tc = (tid & 15) << 3;
    float acc[8][8];
    #pragma unroll
    for (int i = 0; i < 8; i++)
        #pragma unroll
        for (int j = 0; j < 8; j++) acc[i][j] = 0.f;

    for (int k0 = 0; k0 < K; k0 += 8) {
        float4 av = (gARow < M)
            ? *(const float4*)(A + (size_t)gARow * K + k0 + aCol)
            : make_float4(0.f, 0.f, 0.f, 0.f);
        As[(aCol + 0) * 128 + aRow] = av.x;
        As[(aCol + 1) * 128 + aRow] = av.y;
        As[(aCol + 2) * 128 + aRow] = av.z;
        As[(aCol + 3) * 128 + aRow] = av.w;
        *(float4*)(Bs + bRow * 128 + bCol) =
            *(const float4*)(B + (size_t)(k0 + bRow) * Nc + bcol * 128 + bCol);
        __syncthreads();
        #pragma unroll
        for (int kk = 0; kk < 8; kk++) {
            float ar[8], br[8];
            #pragma unroll
            for (int i = 0; i < 8; i++) ar[i] = As[kk * 128 + tr + i];
            #pragma unroll
            for (int j = 0; j < 8; j++) br[j] = Bs[kk * 128 + tc + j];
            #pragma unroll
            for (int i = 0; i < 8; i++)
                #pragma unroll
                for (int j = 0; j < 8; j++) acc[i][j] += ar[i] * br[j];
        }
        __syncthreads();
    }
    #pragma unroll
    for (int i = 0; i < 8; i++) {
        int row = brow * 128 + tr + i;
        if (row >= M) continue;
        #pragma unroll
        for (int j = 0; j < 8; j++) {
            int col = bcol * 128 + tc + j;
            float v = acc[i][j];
            if (bias) v += bias[col];
            if (doRelu) v = (v > 0.f) ? v : 0.f;
            C[(size_t)row * Nc + col] = v;
        }
    }
}

// -------- layer 3 GEMM: g_h3 = h2r(=g_agg2) @ W3  [1024 -> 7] --------
__global__ void k_gemm3(const float* __restrict__ W3) {
    int node = blockIdx.x;
    int warp = threadIdx.x >> 5;   // 0..6 (blockDim=224)
    int lane = threadIdx.x & 31;
    const float* a = g_agg2 + (size_t)node * F2;
    float s = 0.f;
    for (int k = lane; k < F2; k += 32) s += a[k] * W3[k * F3 + warp];
    #pragma unroll
    for (int o = 16; o > 0; o >>= 1) s += __shfl_down_sync(0xffffffff, s, o);
    if (lane == 0) g_h3[node * F3 + warp] = s;
}

// -------- final: z = agg3 + b3 ; out = log_softmax(z) --------
__global__ void k_final(const float* __restrict__ b3, float* __restrict__ out) {
    int i = blockIdx.x * blockDim.x + threadIdx.x;
    if (i >= NN) return;
    float z[F3];
    float m = -INFINITY;
    #pragma unroll
    for (int j = 0; j < F3; j++) {
        z[j] = g_agg3[i * F3 + j] + b3[j];
        m = fmaxf(m, z[j]);
    }
    float ssum = 0.f;
    #pragma unroll
    for (int j = 0; j < F3; j++) ssum += expf(z[j] - m);
    float l = m + logf(ssum);
    #pragma unroll
    for (int j = 0; j < F3; j++) out[i * F3 + j] = z[j] - l;
}

extern "C" void kernel_launch(void* const* d_in, const int* in_sizes, int n_in,
                              void* d_out, int out_size) {
    const float* x   = (const float*)d_in[0];
    const int*   ei  = (const int*)d_in[1];
    const float* W1  = (const float*)d_in[2];
    const float* as1 = (const float*)d_in[3];
    const float* ad1 = (const float*)d_in[4];
    const float* b1  = (const float*)d_in[5];
    const float* W2  = (const float*)d_in[6];
    const float* as2 = (const float*)d_in[7];
    const float* ad2 = (const float*)d_in[8];
    const float* b2  = (const float*)d_in[9];
    const float* W3  = (const float*)d_in[10];
    const float* as3 = (const float*)d_in[11];
    const float* ad3 = (const float*)d_in[12];
    const float* b3  = (const float*)d_in[13];
    float* out = (float*)d_out;

    void *p_agg1, *p_agg2, *p_agg3, *p_h1, *p_h2, *p_h3, *p_v1s, *p_v1d;
    cudaGetSymbolAddress(&p_agg1, g_agg1);
    cudaGetSymbolAddress(&p_agg2, g_agg2);
    cudaGetSymbolAddress(&p_agg3, g_agg3);
    cudaGetSymbolAddress(&p_h1, g_h1);
    cudaGetSymbolAddress(&p_h2, g_h2);
    cudaGetSymbolAddress(&p_h3, g_h3);
    cudaGetSymbolAddress(&p_v1s, g_v1s);
    cudaGetSymbolAddress(&p_v1d, g_v1d);

    const int EB = (EE + 255) / 256;

    // ---- Layer 1: aggregate x in input space (512), then GEMM ----
    k_init<<<2048, 256>>>((float*)p_agg1, (long)NN * F0);
    k_v1<<<F0, 256>>>(W1, as1, ad1);
    k_scores<<<NN, 128>>>(x, (const float*)p_v1s, (const float*)p_v1d, F0);
    k_edge_max<<<EB, 256>>>(ei);
    k_edge_exp<<<EB, 256>>>(ei);
    k_agg1<<<EE, 128>>>(x, ei);
    {
        dim3 g(F1 / 128, (NN + 127) / 128);
        sgemm<<<g, 256>>>((const float*)p_agg1, W1, (float*)p_h1, NN, F1, F0, b1, 1);
    }

    // ---- Layer 2: GEMM first (4096->1024), then aggregate h2 ----
    k_init<<<4096, 256>>>((float*)p_agg2, (long)NN * F2);
    {
        dim3 g(F2 / 128, (NN + 127) / 128);
        sgemm<<<g, 256>>>((const float*)p_h1, W2, (float*)p_h2, NN, F2, F1, nullptr, 0);
    }
    k_scores<<<NN, 128>>>((const float*)p_h2, as2, ad2, F2);
    k_edge_max<<<EB, 256>>>(ei);
    k_edge_exp<<<EB, 256>>>(ei);
    k_agg2<<<EE, 256>>>(ei);
    k_bias_relu2<<<4096, 256>>>(b2);

    // ---- Layer 3: tiny GEMM (1024->7), aggregate, log_softmax ----
    k_init<<<512, 256>>>((float*)p_agg3, (long)NN * F3);
    k_gemm3<<<NN, 224>>>(W3);
    k_scores<<<NN, 128>>>((const float*)p_h3, as3, ad3, F3);
    k_edge_max<<<EB, 256>>>(ei);
    k_edge_exp<<<EB, 256>>>(ei);
    k_agg3<<<EB, 256>>>(ei);
    k_final<<<(NN + 255) / 256, 256>>>(b3, out);
}

// round 4
// speedup vs baseline: 4.1535x; 4.1535x over previous
#include <cuda_runtime.h>
#include <math.h>
#include <stdint.h>

#define NN 10000
#define E0 80000
#define EE 90000
#define F0 512
#define F1 4096
#define F2 1024
#define F3 7
#define NSLOPE 0.2f
#define ENC_NEG_INF 0x807FFFFF

// ---------------- scratch (static device globals; no allocation) ----------------
__device__ float g_agg1[(size_t)NN * F0];
__device__ float g_h1[(size_t)NN * F1];
__device__ float g_h2[(size_t)NN * F2];
__device__ float g_agg2[(size_t)NN * F2];
__device__ float g_h3[NN * F3];
__device__ float g_agg3[NN * F3];
__device__ float g_ssrc[NN], g_sdst[NN];
__device__ int   g_emax[NN];
__device__ float g_denom[NN];
__device__ float g_ex[EE];
__device__ float g_v1s[F0], g_v1d[F0];

__device__ __forceinline__ int f2oi(float f) {
    int i = __float_as_int(f);
    return (i >= 0) ? i : (i ^ 0x7FFFFFFF);
}
__device__ __forceinline__ float oi2f(int i) {
    return (i >= 0) ? __int_as_float(i) : __int_as_float(i ^ 0x7FFFFFFF);
}
__device__ __forceinline__ void edge_sd(const int* __restrict__ ei, int e, int& s, int& d) {
    if (e < E0) { s = ei[e]; d = ei[E0 + e]; }
    else        { s = e - E0; d = e - E0; }
}
__device__ __forceinline__ uint32_t tf32r(float x) {
    uint32_t t;
    asm("cvt.rna.tf32.f32 %0, %1;" : "=r"(t) : "f"(x));
    return t;
}
__device__ __forceinline__ void mma8(float* c, const uint32_t* a, const uint32_t* b) {
    asm volatile(
        "mma.sync.aligned.m16n8k8.row.col.f32.tf32.tf32.f32 "
        "{%0,%1,%2,%3}, {%4,%5,%6,%7}, {%8,%9}, {%0,%1,%2,%3};"
        : "+f"(c[0]), "+f"(c[1]), "+f"(c[2]), "+f"(c[3])
        : "r"(a[0]), "r"(a[1]), "r"(a[2]), "r"(a[3]), "r"(b[0]), "r"(b[1]));
}

// ---------------- small kernels (known-passing skeleton) ----------------
__global__ void k_init(float* __restrict__ agg, long n) {
    long i0 = (long)blockIdx.x * blockDim.x + threadIdx.x;
    long stride = (long)gridDim.x * blockDim.x;
    for (long i = i0; i < n; i += stride) agg[i] = 0.0f;
    if (i0 < NN) { g_emax[i0] = ENC_NEG_INF; g_denom[i0] = 0.0f; }
}

__global__ void k_v1(const float* __restrict__ W1, const float* __restrict__ as,
                     const float* __restrict__ ad) {
    int r = blockIdx.x;
    int tid = threadIdx.x;
    float ss = 0.f, sd = 0.f;
    const float* wrow = W1 + (size_t)r * F1;
    for (int j = tid; j < F1; j += 256) {
        float w = wrow[j];
        ss += w * as[j];
        sd += w * ad[j];
    }
    __shared__ float s1[256], s2[256];
    s1[tid] = ss; s2[tid] = sd;
    __syncthreads();
    for (int s = 128; s > 0; s >>= 1) {
        if (tid < s) { s1[tid] += s1[tid + s]; s2[tid] += s2[tid + s]; }
        __syncthreads();
    }
    if (tid == 0) { g_v1s[r] = s1[0]; g_v1d[r] = s2[0]; }
}

__global__ void k_scores(const float* __restrict__ X, const float* __restrict__ vs,
                         const float* __restrict__ vd, int F) {
    int node = blockIdx.x;
    int tid = threadIdx.x;
    const float* xr = X + (size_t)node * F;
    float ss = 0.f, sd = 0.f;
    for (int j = tid; j < F; j += 128) {
        float x = xr[j];
        ss += x * vs[j];
        sd += x * vd[j];
    }
    __shared__ float s1[128], s2[128];
    s1[tid] = ss; s2[tid] = sd;
    __syncthreads();
    for (int s = 64; s > 0; s >>= 1) {
        if (tid < s) { s1[tid] += s1[tid + s]; s2[tid] += s2[tid + s]; }
        __syncthreads();
    }
    if (tid == 0) { g_ssrc[node] = s1[0]; g_sdst[node] = s2[0]; }
}

__global__ void k_edge_max(const int* __restrict__ ei) {
    int e = blockIdx.x * blockDim.x + threadIdx.x;
    if (e >= EE) return;
    int s, d; edge_sd(ei, e, s, d);
    float v = g_ssrc[s] + g_sdst[d];
    v = (v > 0.f) ? v : NSLOPE * v;
    atomicMax(&g_emax[d], f2oi(v));
}

__global__ void k_edge_exp(const int* __restrict__ ei) {
    int e = blockIdx.x * blockDim.x + threadIdx.x;
    if (e >= EE) return;
    int s, d; edge_sd(ei, e, s, d);
    float v = g_ssrc[s] + g_sdst[d];
    v = (v > 0.f) ? v : NSLOPE * v;
    float ex = __expf(v - oi2f(g_emax[d]));
    g_ex[e] = ex;
    atomicAdd(&g_denom[d], ex);
}

__global__ void k_agg1(const float* __restrict__ x, const int* __restrict__ ei) {
    int e = blockIdx.x;
    int s, d; edge_sd(ei, e, s, d);
    float w = g_ex[e] / g_denom[d];
    float4 xv = ((const float4*)(x + (size_t)s * F0))[threadIdx.x];
    float* o = g_agg1 + (size_t)d * F0 + threadIdx.x * 4;
    atomicAdd(o + 0, w * xv.x);
    atomicAdd(o + 1, w * xv.y);
    atomicAdd(o + 2, w * xv.z);
    atomicAdd(o + 3, w * xv.w);
}

__global__ void k_agg2(const int* __restrict__ ei) {
    int e = blockIdx.x;
    int s, d; edge_sd(ei, e, s, d);
    float w = g_ex[e] / g_denom[d];
    float4 hv = ((const float4*)(g_h2 + (size_t)s * F2))[threadIdx.x];
    float* o = g_agg2 + (size_t)d * F2 + threadIdx.x * 4;
    atomicAdd(o + 0, w * hv.x);
    atomicAdd(o + 1, w * hv.y);
    atomicAdd(o + 2, w * hv.z);
    atomicAdd(o + 3, w * hv.w);
}

__global__ void k_agg3(const int* __restrict__ ei) {
    int e = blockIdx.x * blockDim.x + threadIdx.x;
    if (e >= EE) return;
    int s, d; edge_sd(ei, e, s, d);
    float w = g_ex[e] / g_denom[d];
    #pragma unroll
    for (int j = 0; j < F3; j++)
        atomicAdd(&g_agg3[d * F3 + j], w * g_h3[s * F3 + j]);
}

__global__ void k_bias_relu2(const float* __restrict__ b2) {
    long i0 = (long)blockIdx.x * blockDim.x + threadIdx.x;
    long stride = (long)gridDim.x * blockDim.x;
    long n = (long)NN * F2;
    for (long i = i0; i < n; i += stride) {
        float v = g_agg2[i] + b2[i % F2];
        g_agg2[i] = (v > 0.f) ? v : 0.f;
    }
}

__global__ void k_gemm3(const float* __restrict__ W3) {
    int node = blockIdx.x;
    int warp = threadIdx.x >> 5;
    int lane = threadIdx.x & 31;
    const float* a = g_agg2 + (size_t)node * F2;
    float s = 0.f;
    for (int k = lane; k < F2; k += 32) s += a[k] * W3[k * F3 + warp];
    #pragma unroll
    for (int o = 16; o > 0; o >>= 1) s += __shfl_down_sync(0xffffffff, s, o);
    if (lane == 0) g_h3[node * F3 + warp] = s;
}

__global__ void k_final(const float* __restrict__ b3, float* __restrict__ out) {
    int i = blockIdx.x * blockDim.x + threadIdx.x;
    if (i >= NN) return;
    float z[F3];
    float m = -INFINITY;
    #pragma unroll
    for (int j = 0; j < F3; j++) {
        z[j] = g_agg3[i * F3 + j] + b3[j];
        m = fmaxf(m, z[j]);
    }
    float ssum = 0.f;
    #pragma unroll
    for (int j = 0; j < F3; j++) ssum += expf(z[j] - m);
    float l = m + logf(ssum);
    #pragma unroll
    for (int j = 0; j < F3; j++) out[i * F3 + j] = z[j] - l;
}

// ---------------- tf32 mma.sync GEMM: C[M,Nc] = A[M,K] @ B[K,Nc] ----------------
// BM=128, BN=128, BK=32, 256 threads (8 warps, 4x2: warp_m=wid&3, warp_n=wid>>2).
// Per warp: 32 rows x 64 cols = 2 m16-tiles x 8 n8-tiles of m16n8k8.
// SMEM A: [m][k] rows of 32 + 4 pad (stride 36 words) -> frag reads bank=4g+c (clean).
// SMEM B: [k][n] rows of 128 + 8 pad (stride 136 words) -> frag reads bank=8c+g (clean).
#define SA_STR 36
#define SB_STR 136
#define SM_A0 0
#define SM_A1 (128 * SA_STR)              // 4608
#define SM_B0 (2 * 128 * SA_STR)          // 9216
#define SM_B1 (2 * 128 * SA_STR + 32 * SB_STR)
#define SM_WORDS (2 * 128 * SA_STR + 2 * 32 * SB_STR)   // 17920 words = 71680 B

__device__ __forceinline__ void g_fill(const float* __restrict__ A,
                                       const float* __restrict__ B,
                                       float* sa, float* sbuf,
                                       int row0, int col0, int kt,
                                       int M, int Nc, int K, int tid) {
    // A tile: 128x32, 1024 float4, 4 per thread
    #pragma unroll
    for (int i = 0; i < 4; i++) {
        int idx = i * 256 + tid;
        int m = idx >> 3, k4 = idx & 7;
        float4 v = make_float4(0.f, 0.f, 0.f, 0.f);
        if (row0 + m < M)
            v = *(const float4*)(A + (size_t)(row0 + m) * K + kt * 32 + k4 * 4);
        uint4 t = make_uint4(tf32r(v.x), tf32r(v.y), tf32r(v.z), tf32r(v.w));
        *(uint4*)(sa + m * SA_STR + k4 * 4) = t;
    }
    // B tile: 32x128, 1024 float4, 4 per thread
    #pragma unroll
    for (int i = 0; i < 4; i++) {
        int idx = i * 256 + tid;
        int k = idx >> 5, n4 = idx & 31;
        float4 v = *(const float4*)(B + (size_t)(kt * 32 + k) * Nc + col0 + n4 * 4);
        uint4 t = make_uint4(tf32r(v.x), tf32r(v.y), tf32r(v.z), tf32r(v.w));
        *(uint4*)(sbuf + k * SB_STR + n4 * 4) = t;
    }
}

__global__ void __launch_bounds__(256, 2)
tc_gemm(const float* __restrict__ A, const float* __restrict__ B, float* __restrict__ C,
        int M, int Nc, int K, const float* __restrict__ bias, int doRelu) {
    extern __shared__ float sm[];
    int tid = threadIdx.x;
    int lane = tid & 31, wid = tid >> 5;
    int warp_m = wid & 3, warp_n = wid >> 2;
    int g = lane >> 2, c = lane & 3;
    int row0 = blockIdx.y * 128, col0 = blockIdx.x * 128;

    float acc[2][8][4];
    #pragma unroll
    for (int t = 0; t < 2; t++)
        #pragma unroll
        for (int u = 0; u < 8; u++)
            #pragma unroll
            for (int j = 0; j < 4; j++) acc[t][u][j] = 0.f;

    const int KT = K >> 5;
    g_fill(A, B, sm + SM_A0, sm + SM_B0, row0, col0, 0, M, Nc, K, tid);
    __syncthreads();

    for (int kt = 0; kt < KT; kt++) {
        int buf = kt & 1;
        if (kt + 1 < KT)
            g_fill(A, B, sm + (buf ? SM_A0 : SM_A1), sm + (buf ? SM_B0 : SM_B1),
                   row0, col0, kt + 1, M, Nc, K, tid);
        const float* sa = sm + (buf ? SM_A1 : SM_A0);
        const float* sb = sm + (buf ? SM_B1 : SM_B0);
        #pragma unroll
        for (int ks = 0; ks < 4; ks++) {
            uint32_t af[2][4];
            #pragma unroll
            for (int t = 0; t < 2; t++) {
                const float* pa = sa + (warp_m * 32 + t * 16 + g) * SA_STR + ks * 8 + c;
                af[t][0] = __float_as_uint(pa[0]);
                af[t][1] = __float_as_uint(pa[8 * SA_STR]);
                af[t][2] = __float_as_uint(pa[4]);
                af[t][3] = __float_as_uint(pa[8 * SA_STR + 4]);
            }
            uint32_t bf[8][2];
            #pragma unroll
            for (int u = 0; u < 8; u++) {
                const float* pb = sb + (ks * 8 + c) * SB_STR + warp_n * 64 + u * 8 + g;
                bf[u][0] = __float_as_uint(pb[0]);
                bf[u][1] = __float_as_uint(pb[4 * SB_STR]);
            }
            #pragma unroll
            for (int t = 0; t < 2; t++)
                #pragma unroll
                for (int u = 0; u < 8; u++)
                    mma8(acc[t][u], af[t], bf[u]);
        }
        __syncthreads();
    }

    // epilogue
    #pragma unroll
    for (int t = 0; t < 2; t++) {
        int r0 = row0 + warp_m * 32 + t * 16 + g;
        #pragma unroll
        for (int u = 0; u < 8; u++) {
            int cc = col0 + warp_n * 64 + u * 8 + 2 * c;
            float2 v0 = make_float2(acc[t][u][0], acc[t][u][1]);
            float2 v1 = make_float2(acc[t][u][2], acc[t][u][3]);
            if (bias) {
                float b0v = bias[cc], b1v = bias[cc + 1];
                v0.x += b0v; v0.y += b1v;
                v1.x += b0v; v1.y += b1v;
            }
            if (doRelu) {
                v0.x = fmaxf(v0.x, 0.f); v0.y = fmaxf(v0.y, 0.f);
                v1.x = fmaxf(v1.x, 0.f); v1.y = fmaxf(v1.y, 0.f);
            }
            if (r0 < M)     *(float2*)(C + (size_t)r0 * Nc + cc) = v0;
            if (r0 + 8 < M) *(float2*)(C + (size_t)(r0 + 8) * Nc + cc) = v1;
        }
    }
}

// ---------------- launch ----------------
extern "C" void kernel_launch(void* const* d_in, const int* in_sizes, int n_in,
                              void* d_out, int out_size) {
    const float* x   = (const float*)d_in[0];
    const int*   ei  = (const int*)d_in[1];
    const float* W1  = (const float*)d_in[2];
    const float* as1 = (const float*)d_in[3];
    const float* ad1 = (const float*)d_in[4];
    const float* b1  = (const float*)d_in[5];
    const float* W2  = (const float*)d_in[6];
    const float* as2 = (const float*)d_in[7];
    const float* ad2 = (const float*)d_in[8];
    const float* b2  = (const float*)d_in[9];
    const float* W3  = (const float*)d_in[10];
    const float* as3 = (const float*)d_in[11];
    const float* ad3 = (const float*)d_in[12];
    const float* b3  = (const float*)d_in[13];
    float* out = (float*)d_out;

    void *p_agg1, *p_agg2, *p_agg3, *p_h1, *p_h2, *p_h3, *p_v1s, *p_v1d;
    cudaGetSymbolAddress(&p_agg1, g_agg1);
    cudaGetSymbolAddress(&p_agg2, g_agg2);
    cudaGetSymbolAddress(&p_agg3, g_agg3);
    cudaGetSymbolAddress(&p_h1, g_h1);
    cudaGetSymbolAddress(&p_h2, g_h2);
    cudaGetSymbolAddress(&p_h3, g_h3);
    cudaGetSymbolAddress(&p_v1s, g_v1s);
    cudaGetSymbolAddress(&p_v1d, g_v1d);

    cudaFuncSetAttribute(tc_gemm, cudaFuncAttributeMaxDynamicSharedMemorySize,
                         SM_WORDS * (int)sizeof(float));

    const int EB = (EE + 255) / 256;

    // ---- Layer 1: aggregate x in input space (512), then tf32 GEMM ----
    k_init<<<2048, 256>>>((float*)p_agg1, (long)NN * F0);
    k_v1<<<F0, 256>>>(W1, as1, ad1);
    k_scores<<<NN, 128>>>(x, (const float*)p_v1s, (const float*)p_v1d, F0);
    k_edge_max<<<EB, 256>>>(ei);
    k_edge_exp<<<EB, 256>>>(ei);
    k_agg1<<<EE, 128>>>(x, ei);
    {
        dim3 grd(F1 / 128, (NN + 127) / 128);
        tc_gemm<<<grd, 256, SM_WORDS * sizeof(float)>>>(
            (const float*)p_agg1, W1, (float*)p_h1, NN, F1, F0, b1, 1);
    }

    // ---- Layer 2: tf32 GEMM (4096->1024), then aggregate h2 ----
    k_init<<<4096, 256>>>((float*)p_agg2, (long)NN * F2);
    {
        dim3 grd(F2 / 128, (NN + 127) / 128);
        tc_gemm<<<grd, 256, SM_WORDS * sizeof(float)>>>(
            (const float*)p_h1, W2, (float*)p_h2, NN, F2, F1, nullptr, 0);
    }
    k_scores<<<NN, 128>>>((const float*)p_h2, as2, ad2, F2);
    k_edge_max<<<EB, 256>>>(ei);
    k_edge_exp<<<EB, 256>>>(ei);
    k_agg2<<<EE, 256>>>(ei);
    k_bias_relu2<<<4096, 256>>>(b2);

    // ---- Layer 3: tiny GEMM (1024->7), aggregate, log_softmax ----
    k_init<<<512, 256>>>((float*)p_agg3, (long)NN * F3);
    k_gemm3<<<NN, 224>>>(W3);
    k_scores<<<NN, 128>>>((const float*)p_h3, as3, ad3, F3);
    k_edge_max<<<EB, 256>>>(ei);
    k_edge_exp<<<EB, 256>>>(ei);
    k_agg3<<<EB, 256>>>(ei);
    k_final<<<(NN + 255) / 256, 256>>>(b3, out);
}

// round 5
// speedup vs baseline: 4.9429x; 1.1901x over previous
#include <cuda_runtime.h>
#include <math.h>
#include <stdint.h>

#define NN 10000
#define E0 80000
#define EE 90000
#define F0 512
#define F1 4096
#define F2 1024
#define F3 7
#define NSLOPE 0.2f

// ---------------- scratch (static device globals; no allocation) ----------------
__device__ float g_agg1[(size_t)NN * F0];
__device__ float g_h1[(size_t)NN * F1];
__device__ float g_h2[(size_t)NN * F2];
__device__ float g_agg2[(size_t)NN * F2];
__device__ float g_h3[NN * F3];
__device__ float g_ssrc[NN], g_sdst[NN];
__device__ float g_v1s[F0], g_v1d[F0];
// CSR by destination
__device__ int g_deg[NN];
__device__ int g_cursor[NN];
__device__ int g_off[NN + 1];
__device__ int g_csr[EE];

__device__ __forceinline__ void edge_sd(const int* __restrict__ ei, int e, int& s, int& d) {
    if (e < E0) { s = ei[e]; d = ei[E0 + e]; }
    else        { s = e - E0; d = e - E0; }
}
__device__ __forceinline__ uint32_t tf32r(float x) {
    uint32_t t;
    asm("cvt.rna.tf32.f32 %0, %1;" : "=r"(t) : "f"(x));
    return t;
}
__device__ __forceinline__ uint32_t smem_u32(const void* p) {
    uint32_t a;
    asm("{ .reg .u64 t; cvta.to.shared.u64 t, %1; cvt.u32.u64 %0, t; }" : "=r"(a) : "l"(p));
    return a;
}
__device__ __forceinline__ void cpa16(uint32_t dst, const void* src, int sz) {
    asm volatile("cp.async.cg.shared.global [%0], [%1], 16, %2;"
                 :: "r"(dst), "l"(src), "r"(sz));
}
__device__ __forceinline__ void mma8(float* c, const uint32_t* a, const uint32_t* b) {
    asm volatile(
        "mma.sync.aligned.m16n8k8.row.col.f32.tf32.tf32.f32 "
        "{%0,%1,%2,%3}, {%4,%5,%6,%7}, {%8,%9}, {%0,%1,%2,%3};"
        : "+f"(c[0]), "+f"(c[1]), "+f"(c[2]), "+f"(c[3])
        : "r"(a[0]), "r"(a[1]), "r"(a[2]), "r"(a[3]), "r"(b[0]), "r"(b[1]));
}
__device__ __forceinline__ float lrelu(float v) { return (v > 0.f) ? v : NSLOPE * v; }

// ---------------- CSR build ----------------
__global__ void k_zerodeg() {
    int i = blockIdx.x * blockDim.x + threadIdx.x;
    if (i < NN) g_deg[i] = 0;
}
__global__ void k_deg(const int* __restrict__ ei) {
    int e = blockIdx.x * blockDim.x + threadIdx.x;
    if (e >= EE) return;
    int s, d; edge_sd(ei, e, s, d);
    atomicAdd(&g_deg[d], 1);
}
__global__ void k_scan() {   // single block, 1024 threads, chunk=10
    __shared__ int sh[1024];
    int tid = threadIdx.x;
    int base = tid * 10;
    int cnt[10]; int local = 0;
    #pragma unroll
    for (int i = 0; i < 10; i++) {
        int idx = base + i;
        int c = (idx < NN) ? g_deg[idx] : 0;
        cnt[i] = local; local += c;
    }
    sh[tid] = local;
    __syncthreads();
    for (int off = 1; off < 1024; off <<= 1) {
        int v = (tid >= off) ? sh[tid - off] : 0;
        __syncthreads();
        sh[tid] += v;
        __syncthreads();
    }
    int start = sh[tid] - local;
    #pragma unroll
    for (int i = 0; i < 10; i++) {
        int idx = base + i;
        if (idx < NN) { g_off[idx] = start + cnt[i]; g_cursor[idx] = 0; }
    }
    if (tid == 1023) g_off[NN] = sh[1023];
}
__global__ void k_fill(const int* __restrict__ ei) {
    int e = blockIdx.x * blockDim.x + threadIdx.x;
    if (e >= EE) return;
    int s, d; edge_sd(ei, e, s, d);
    int p = atomicAdd(&g_cursor[d], 1);
    g_csr[g_off[d] + p] = s;
}

// ---------------- attention-vector & node-score kernels ----------------
__global__ void k_v1(const float* __restrict__ W1, const float* __restrict__ as,
                     const float* __restrict__ ad) {
    int r = blockIdx.x;
    int tid = threadIdx.x;
    float ss = 0.f, sd = 0.f;
    const float* wrow = W1 + (size_t)r * F1;
    for (int j = tid; j < F1; j += 256) {
        float w = wrow[j];
        ss += w * as[j];
        sd += w * ad[j];
    }
    __shared__ float s1[256], s2[256];
    s1[tid] = ss; s2[tid] = sd;
    __syncthreads();
    for (int s = 128; s > 0; s >>= 1) {
        if (tid < s) { s1[tid] += s1[tid + s]; s2[tid] += s2[tid + s]; }
        __syncthreads();
    }
    if (tid == 0) { g_v1s[r] = s1[0]; g_v1d[r] = s2[0]; }
}

__global__ void k_scores(const float* __restrict__ X, const float* __restrict__ vs,
                         const float* __restrict__ vd, int F) {
    int node = blockIdx.x;
    int tid = threadIdx.x;      // 128
    const float* xr = X + (size_t)node * F;
    float ss = 0.f, sd = 0.f;
    for (int j = tid; j < F; j += 128) {
        float x = xr[j];
        ss += x * vs[j];
        sd += x * vd[j];
    }
    __shared__ float s1[128], s2[128];
    s1[tid] = ss; s2[tid] = sd;
    __syncthreads();
    for (int s = 64; s > 0; s >>= 1) {
        if (tid < s) { s1[tid] += s1[tid + s]; s2[tid] += s2[tid + s]; }
        __syncthreads();
    }
    if (tid == 0) { g_ssrc[node] = s1[0]; g_sdst[node] = s2[0]; }
}

// ---------------- gather aggregation (softmax fused, no atomics) ----------------
__global__ void k_gat1(const float* __restrict__ x) {
    int n = blockIdx.x, tid = threadIdx.x;   // 128 threads
    int rs = g_off[n], re = g_off[n + 1];
    float sdv = g_sdst[n];
    __shared__ float red[128];
    float m = -1e30f;
    for (int j = rs + tid; j < re; j += 128)
        m = fmaxf(m, lrelu(g_ssrc[g_csr[j]] + sdv));
    red[tid] = m; __syncthreads();
    for (int s = 64; s > 0; s >>= 1) {
        if (tid < s) red[tid] = fmaxf(red[tid], red[tid + s]);
        __syncthreads();
    }
    m = red[0]; __syncthreads();
    float den = 0.f;
    for (int j = rs + tid; j < re; j += 128)
        den += __expf(lrelu(g_ssrc[g_csr[j]] + sdv) - m);
    red[tid] = den; __syncthreads();
    for (int s = 64; s > 0; s >>= 1) {
        if (tid < s) red[tid] += red[tid + s];
        __syncthreads();
    }
    float inv = 1.0f / red[0];
    float4 acc = make_float4(0.f, 0.f, 0.f, 0.f);
    for (int j = rs; j < re; j++) {
        int s = g_csr[j];
        float w = __expf(lrelu(g_ssrc[s] + sdv) - m) * inv;
        float4 xv = ((const float4*)(x + (size_t)s * F0))[tid];
        acc.x += w * xv.x; acc.y += w * xv.y;
        acc.z += w * xv.z; acc.w += w * xv.w;
    }
    ((float4*)(g_agg1 + (size_t)n * F0))[tid] = acc;
}

__global__ void k_gat2(const float* __restrict__ b2) {
    int n = blockIdx.x, tid = threadIdx.x;   // 256 threads
    int rs = g_off[n], re = g_off[n + 1];
    float sdv = g_sdst[n];
    __shared__ float red[256];
    float m = -1e30f;
    for (int j = rs + tid; j < re; j += 256)
        m = fmaxf(m, lrelu(g_ssrc[g_csr[j]] + sdv));
    red[tid] = m; __syncthreads();
    for (int s = 128; s > 0; s >>= 1) {
        if (tid < s) red[tid] = fmaxf(red[tid], red[tid + s]);
        __syncthreads();
    }
    m = red[0]; __syncthreads();
    float den = 0.f;
    for (int j = rs + tid; j < re; j += 256)
        den += __expf(lrelu(g_ssrc[g_csr[j]] + sdv) - m);
    red[tid] = den; __syncthreads();
    for (int s = 128; s > 0; s >>= 1) {
        if (tid < s) red[tid] += red[tid + s];
        __syncthreads();
    }
    float inv = 1.0f / red[0];
    float4 acc = make_float4(0.f, 0.f, 0.f, 0.f);
    for (int j = rs; j < re; j++) {
        int s = g_csr[j];
        float w = __expf(lrelu(g_ssrc[s] + sdv) - m) * inv;
        float4 hv = ((const float4*)(g_h2 + (size_t)s * F2))[tid];
        acc.x += w * hv.x; acc.y += w * hv.y;
        acc.z += w * hv.z; acc.w += w * hv.w;
    }
    float4 bv = ((const float4*)b2)[tid];
    acc.x = fmaxf(acc.x + bv.x, 0.f);
    acc.y = fmaxf(acc.y + bv.y, 0.f);
    acc.z = fmaxf(acc.z + bv.z, 0.f);
    acc.w = fmaxf(acc.w + bv.w, 0.f);
    ((float4*)(g_agg2 + (size_t)n * F2))[tid] = acc;
}

// ---------------- layer 3: tiny GEMM then fused gather + log_softmax ----------------
__global__ void k_gemm3(const float* __restrict__ W3) {
    int node = blockIdx.x;
    int warp = threadIdx.x >> 5;   // 0..6
    int lane = threadIdx.x & 31;
    const float* a = g_agg2 + (size_t)node * F2;
    float s = 0.f;
    for (int k = lane; k < F2; k += 32) s += a[k] * W3[k * F3 + warp];
    #pragma unroll
    for (int o = 16; o > 0; o >>= 1) s += __shfl_down_sync(0xffffffff, s, o);
    if (lane == 0) g_h3[node * F3 + warp] = s;
}

__global__ void k_gat3f(const float* __restrict__ b3, float* __restrict__ out) {
    int wg = (blockIdx.x * blockDim.x + threadIdx.x) >> 5;
    if (wg >= NN) return;
    int lane = threadIdx.x & 31;
    int rs = g_off[wg], re = g_off[wg + 1];
    float sdv = g_sdst[wg];
    float m = -1e30f;
    for (int j = rs + lane; j < re; j += 32)
        m = fmaxf(m, lrelu(g_ssrc[g_csr[j]] + sdv));
    #pragma unroll
    for (int o = 16; o > 0; o >>= 1) m = fmaxf(m, __shfl_xor_sync(0xffffffff, m, o));
    float den = 0.f;
    for (int j = rs + lane; j < re; j += 32)
        den += __expf(lrelu(g_ssrc[g_csr[j]] + sdv) - m);
    #pragma unroll
    for (int o = 16; o > 0; o >>= 1) den += __shfl_xor_sync(0xffffffff, den, o);
    float inv = 1.0f / den;
    float acc = 0.f;
    for (int j = rs; j < re; j++) {
        int s = g_csr[j];
        float w = __expf(lrelu(g_ssrc[s] + sdv) - m) * inv;
        if (lane < F3) acc += w * g_h3[s * F3 + lane];
    }
    float z = (lane < F3) ? acc + b3[lane] : -1e30f;
    float mz = z;
    #pragma unroll
    for (int o = 16; o > 0; o >>= 1) mz = fmaxf(mz, __shfl_xor_sync(0xffffffff, mz, o));
    float e = (lane < F3) ? expf(z - mz) : 0.f;
    #pragma unroll
    for (int o = 16; o > 0; o >>= 1) e += __shfl_xor_sync(0xffffffff, e, o);
    float l = mz + logf(e);
    if (lane < F3) out[wg * F3 + lane] = z - l;
}

// ---------------- tf32 mma.sync GEMM, cp.async pipelined ----------------
// C[M,Nc] = A[M,K] @ B[K,Nc]. BM=128, BN=256, BK=32, 512 threads (16 warps, 4x4).
// Warp tile 32x64 = 2 m16 x 8 n8 of m16n8k8.
// SMEM A: [m][k] stride 36 words (frag banks 4g+c clean).
// SMEM B: [k][n] stride 264 words (frag banks 8c+g clean; 264%32==8, 264%8==0).
#define SA_STR 36
#define SB_STR 264
#define ST_A (128 * SA_STR)          // 4608 words
#define ST_B (32 * SB_STR)           // 8448 words
#define ST_WORDS (ST_A + ST_B)       // 13056 words per stage
#define SM_BYTES (2 * ST_WORDS * 4)  // 104448 bytes

__device__ __forceinline__ void g_fill_async(const float* __restrict__ A,
                                             const float* __restrict__ B,
                                             uint32_t sa_u, uint32_t sb_u,
                                             int row0, int col0, int kt,
                                             int M, int Nc, int K, int tid) {
    #pragma unroll
    for (int i = 0; i < 2; i++) {          // A: 1024 float4 / 512 thr
        int idx = i * 512 + tid;
        int m = idx >> 3, k4 = idx & 7;
        int gr = row0 + m;
        int ok = gr < M;
        const float* src = A + (size_t)(ok ? gr : row0) * K + kt * 32 + k4 * 4;
        cpa16(sa_u + (uint32_t)(m * SA_STR + k4 * 4) * 4, src, ok ? 16 : 0);
    }
    #pragma unroll
    for (int i = 0; i < 4; i++) {          // B: 2048 float4 / 512 thr
        int idx = i * 512 + tid;
        int k = idx >> 6, n4 = idx & 63;
        const float* src = B + (size_t)(kt * 32 + k) * Nc + col0 + n4 * 4;
        cpa16(sb_u + (uint32_t)(k * SB_STR + n4 * 4) * 4, src, 16);
    }
    asm volatile("cp.async.commit_group;" ::: "memory");
}

__global__ void __launch_bounds__(512, 1)
tc_gemm(const float* __restrict__ A, const float* __restrict__ B, float* __restrict__ C,
        int M, int Nc, int K, const float* __restrict__ bias, int doRelu) {
    extern __shared__ float sm[];
    uint32_t smu = smem_u32(sm);
    int tid = threadIdx.x;
    int lane = tid & 31, wid = tid >> 5;
    int warp_m = wid & 3, warp_n = wid >> 2;   // 4 x 4
    int g = lane >> 2, c = lane & 3;
    int row0 = blockIdx.y * 128, col0 = blockIdx.x * 256;

    // stage word offsets: A0 | B0 | A1 | B1
    const uint32_t A_off[2] = { 0u, (uint32_t)ST_WORDS };
    const uint32_t B_off[2] = { (uint32_t)ST_A, (uint32_t)(ST_WORDS + ST_A) };

    float acc[2][8][4];
    #pragma unroll
    for (int t = 0; t < 2; t++)
        #pragma unroll
        for (int u = 0; u < 8; u++)
            #pragma unroll
            for (int j = 0; j < 4; j++) acc[t][u][j] = 0.f;

    const int KT = K >> 5;
    g_fill_async(A, B, smu + A_off[0] * 4, smu + B_off[0] * 4, row0, col0, 0, M, Nc, K, tid);

    for (int kt = 0; kt < KT; kt++) {
        int buf = kt & 1;
        if (kt + 1 < KT) {
            g_fill_async(A, B, smu + A_off[buf ^ 1] * 4, smu + B_off[buf ^ 1] * 4,
                         row0, col0, kt + 1, M, Nc, K, tid);
            asm volatile("cp.async.wait_group 1;" ::: "memory");
        } else {
            asm volatile("cp.async.wait_group 0;" ::: "memory");
        }
        __syncthreads();
        const float* sa = sm + A_off[buf];
        const float* sb = sm + B_off[buf];
        #pragma unroll
        for (int ks = 0; ks < 4; ks++) {
            uint32_t af[2][4];
            #pragma unroll
            for (int t = 0; t < 2; t++) {
                const float* pa = sa + (warp_m * 32 + t * 16 + g) * SA_STR + ks * 8 + c;
                af[t][0] = tf32r(pa[0]);
                af[t][1] = tf32r(pa[8 * SA_STR]);
                af[t][2] = tf32r(pa[4]);
                af[t][3] = tf32r(pa[8 * SA_STR + 4]);
            }
            uint32_t bf[8][2];
            #pragma unroll
            for (int u = 0; u < 8; u++) {
                const float* pb = sb + (ks * 8 + c) * SB_STR + warp_n * 64 + u * 8 + g;
                bf[u][0] = tf32r(pb[0]);
                bf[u][1] = tf32r(pb[4 * SB_STR]);
            }
            #pragma unroll
            for (int t = 0; t < 2; t++)
                #pragma unroll
                for (int u = 0; u < 8; u++)
                    mma8(acc[t][u], af[t], bf[u]);
        }
        __syncthreads();
    }

    // epilogue
    #pragma unroll
    for (int t = 0; t < 2; t++) {
        int r0 = row0 + warp_m * 32 + t * 16 + g;
        #pragma unroll
        for (int u = 0; u < 8; u++) {
            int cc = col0 + warp_n * 64 + u * 8 + 2 * c;
            float2 v0 = make_float2(acc[t][u][0], acc[t][u][1]);
            float2 v1 = make_float2(acc[t][u][2], acc[t][u][3]);
            if (bias) {
                float b0v = bias[cc], b1v = bias[cc + 1];
                v0.x += b0v; v0.y += b1v;
                v1.x += b0v; v1.y += b1v;
            }
            if (doRelu) {
                v0.x = fmaxf(v0.x, 0.f); v0.y = fmaxf(v0.y, 0.f);
                v1.x = fmaxf(v1.x, 0.f); v1.y = fmaxf(v1.y, 0.f);
            }
            if (r0 < M)     *(float2*)(C + (size_t)r0 * Nc + cc) = v0;
            if (r0 + 8 < M) *(float2*)(C + (size_t)(r0 + 8) * Nc + cc) = v1;
        }
    }
}

// ---------------- launch ----------------
extern "C" void kernel_launch(void* const* d_in, const int* in_sizes, int n_in,
                              void* d_out, int out_size) {
    const float* x   = (const float*)d_in[0];
    const int*   ei  = (const int*)d_in[1];
    const float* W1  = (const float*)d_in[2];
    const float* as1 = (const float*)d_in[3];
    const float* ad1 = (const float*)d_in[4];
    const float* b1  = (const float*)d_in[5];
    const float* W2  = (const float*)d_in[6];
    const float* as2 = (const float*)d_in[7];
    const float* ad2 = (const float*)d_in[8];
    const float* b2  = (const float*)d_in[9];
    const float* W3  = (const float*)d_in[10];
    const float* as3 = (const float*)d_in[11];
    const float* ad3 = (const float*)d_in[12];
    const float* b3  = (const float*)d_in[13];
    float* out = (float*)d_out;

    void *p_agg1, *p_agg2, *p_h1, *p_h2, *p_h3, *p_v1s, *p_v1d;
    cudaGetSymbolAddress(&p_agg1, g_agg1);
    cudaGetSymbolAddress(&p_agg2, g_agg2);
    cudaGetSymbolAddress(&p_h1, g_h1);
    cudaGetSymbolAddress(&p_h2, g_h2);
    cudaGetSymbolAddress(&p_h3, g_h3);
    cudaGetSymbolAddress(&p_v1s, g_v1s);
    cudaGetSymbolAddress(&p_v1d, g_v1d);

    cudaFuncSetAttribute(tc_gemm, cudaFuncAttributeMaxDynamicSharedMemorySize, SM_BYTES);

    const int EB = (EE + 255) / 256;
    const int MB = (NN + 127) / 128;

    // ---- CSR build (reused by all 3 layers) ----
    k_zerodeg<<<(NN + 255) / 256, 256>>>();
    k_deg<<<EB, 256>>>(ei);
    k_scan<<<1, 1024>>>();
    k_fill<<<EB, 256>>>(ei);

    // ---- Layer 1: scores on x, gather in x-space (512), then GEMM ----
    k_v1<<<F0, 256>>>(W1, as1, ad1);
    k_scores<<<NN, 128>>>(x, (const float*)p_v1s, (const float*)p_v1d, F0);
    k_gat1<<<NN, 128>>>(x);
    {
        dim3 grd(F1 / 256, MB);
        tc_gemm<<<grd, 512, SM_BYTES>>>((const float*)p_agg1, W1, (float*)p_h1,
                                        NN, F1, F0, b1, 1);
    }

    // ---- Layer 2: GEMM (4096->1024), scores, gather (+bias+relu fused) ----
    {
        dim3 grd(F2 / 256, MB);
        tc_gemm<<<grd, 512, SM_BYTES>>>((const float*)p_h1, W2, (float*)p_h2,
                                        NN, F2, F1, nullptr, 0);
    }
    k_scores<<<NN, 128>>>((const float*)p_h2, as2, ad2, F2);
    k_gat2<<<NN, 256>>>(b2);

    // ---- Layer 3: tiny GEMM (1024->7), scores, fused gather+log_softmax ----
    k_gemm3<<<NN, 224>>>(W3);
    k_scores<<<NN, 128>>>((const float*)p_h3, as3, ad3, F3);
    k_gat3f<<<(NN * 32 + 255) / 256, 256>>>(b3, out);
}

// round 6
// speedup vs baseline: 5.1585x; 1.0436x over previous
#include <cuda_runtime.h>
#include <math.h>
#include <stdint.h>

#define NN 10000
#define E0 80000
#define EE 90000
#define F0 512
#define F1 4096
#define F2 1024
#define F3 7
#define NSLOPE 0.2f

// ---------------- scratch (static device globals; no allocation) ----------------
__device__ float g_agg1[(size_t)NN * F0];
__device__ float g_h1[(size_t)NN * F1];
__device__ float g_h2[(size_t)NN * F2];
__device__ float g_agg2[(size_t)NN * F2];
__device__ float g_h3[NN * F3];
__device__ float g_ssrc[NN], g_sdst[NN];
__device__ float g_v1s[F0], g_v1d[F0];
// CSR by destination
__device__ int g_deg[NN];
__device__ int g_cursor[NN];
__device__ int g_off[NN + 1];
__device__ int g_csr[EE];

__device__ __forceinline__ void edge_sd(const int* __restrict__ ei, int e, int& s, int& d) {
    if (e < E0) { s = ei[e]; d = ei[E0 + e]; }
    else        { s = e - E0; d = e - E0; }
}
__device__ __forceinline__ uint32_t tf32r(float x) {
    uint32_t t;
    asm("cvt.rna.tf32.f32 %0, %1;" : "=r"(t) : "f"(x));
    return t;
}
__device__ __forceinline__ uint32_t smem_u32(const void* p) {
    uint32_t a;
    asm("{ .reg .u64 t; cvta.to.shared.u64 t, %1; cvt.u32.u64 %0, t; }" : "=r"(a) : "l"(p));
    return a;
}
__device__ __forceinline__ void cpa16(uint32_t dst, const void* src, int sz) {
    asm volatile("cp.async.cg.shared.global [%0], [%1], 16, %2;"
                 :: "r"(dst), "l"(src), "r"(sz));
}
__device__ __forceinline__ void mma8(float* c, const uint32_t* a, const uint32_t* b) {
    asm volatile(
        "mma.sync.aligned.m16n8k8.row.col.f32.tf32.tf32.f32 "
        "{%0,%1,%2,%3}, {%4,%5,%6,%7}, {%8,%9}, {%0,%1,%2,%3};"
        : "+f"(c[0]), "+f"(c[1]), "+f"(c[2]), "+f"(c[3])
        : "r"(a[0]), "r"(a[1]), "r"(a[2]), "r"(a[3]), "r"(b[0]), "r"(b[1]));
}
__device__ __forceinline__ float lrelu(float v) { return (v > 0.f) ? v : NSLOPE * v; }

// ---------------- CSR build ----------------
__global__ void k_zerodeg() {
    int i = blockIdx.x * blockDim.x + threadIdx.x;
    if (i < NN) g_deg[i] = 0;
}
__global__ void k_deg(const int* __restrict__ ei) {
    int e = blockIdx.x * blockDim.x + threadIdx.x;
    if (e >= EE) return;
    int s, d; edge_sd(ei, e, s, d);
    atomicAdd(&g_deg[d], 1);
}
__global__ void k_scan() {   // single block, 1024 threads, chunk=10
    __shared__ int sh[1024];
    int tid = threadIdx.x;
    int base = tid * 10;
    int cnt[10]; int local = 0;
    #pragma unroll
    for (int i = 0; i < 10; i++) {
        int idx = base + i;
        int c = (idx < NN) ? g_deg[idx] : 0;
        cnt[i] = local; local += c;
    }
    sh[tid] = local;
    __syncthreads();
    for (int off = 1; off < 1024; off <<= 1) {
        int v = (tid >= off) ? sh[tid - off] : 0;
        __syncthreads();
        sh[tid] += v;
        __syncthreads();
    }
    int start = sh[tid] - local;
    #pragma unroll
    for (int i = 0; i < 10; i++) {
        int idx = base + i;
        if (idx < NN) { g_off[idx] = start + cnt[i]; g_cursor[idx] = 0; }
    }
    if (tid == 1023) g_off[NN] = sh[1023];
}
__global__ void k_fill(const int* __restrict__ ei) {
    int e = blockIdx.x * blockDim.x + threadIdx.x;
    if (e >= EE) return;
    int s, d; edge_sd(ei, e, s, d);
    int p = atomicAdd(&g_cursor[d], 1);
    g_csr[g_off[d] + p] = s;
}

// ---------------- attention-vector & node-score kernels ----------------
__global__ void k_v1(const float* __restrict__ W1, const float* __restrict__ as,
                     const float* __restrict__ ad) {
    int r = blockIdx.x;
    int tid = threadIdx.x;
    float ss = 0.f, sd = 0.f;
    const float* wrow = W1 + (size_t)r * F1;
    for (int j = tid; j < F1; j += 256) {
        float w = wrow[j];
        ss += w * as[j];
        sd += w * ad[j];
    }
    __shared__ float s1[256], s2[256];
    s1[tid] = ss; s2[tid] = sd;
    __syncthreads();
    for (int s = 128; s > 0; s >>= 1) {
        if (tid < s) { s1[tid] += s1[tid + s]; s2[tid] += s2[tid + s]; }
        __syncthreads();
    }
    if (tid == 0) { g_v1s[r] = s1[0]; g_v1d[r] = s2[0]; }
}

__global__ void k_scores(const float* __restrict__ X, const float* __restrict__ vs,
                         const float* __restrict__ vd, int F) {
    int node = blockIdx.x;
    int tid = threadIdx.x;      // 128
    const float* xr = X + (size_t)node * F;
    float ss = 0.f, sd = 0.f;
    for (int j = tid; j < F; j += 128) {
        float x = xr[j];
        ss += x * vs[j];
        sd += x * vd[j];
    }
    __shared__ float s1[128], s2[128];
    s1[tid] = ss; s2[tid] = sd;
    __syncthreads();
    for (int s = 64; s > 0; s >>= 1) {
        if (tid < s) { s1[tid] += s1[tid + s]; s2[tid] += s2[tid + s]; }
        __syncthreads();
    }
    if (tid == 0) { g_ssrc[node] = s1[0]; g_sdst[node] = s2[0]; }
}

// ---------------- gather aggregation (softmax fused, no atomics) ----------------
__global__ void k_gat1(const float* __restrict__ x) {
    int n = blockIdx.x, tid = threadIdx.x;   // 128 threads
    int rs = g_off[n], re = g_off[n + 1];
    float sdv = g_sdst[n];
    __shared__ float red[128];
    float m = -1e30f;
    for (int j = rs + tid; j < re; j += 128)
        m = fmaxf(m, lrelu(g_ssrc[g_csr[j]] + sdv));
    red[tid] = m; __syncthreads();
    for (int s = 64; s > 0; s >>= 1) {
        if (tid < s) red[tid] = fmaxf(red[tid], red[tid + s]);
        __syncthreads();
    }
    m = red[0]; __syncthreads();
    float den = 0.f;
    for (int j = rs + tid; j < re; j += 128)
        den += __expf(lrelu(g_ssrc[g_csr[j]] + sdv) - m);
    red[tid] = den; __syncthreads();
    for (int s = 64; s > 0; s >>= 1) {
        if (tid < s) red[tid] += red[tid + s];
        __syncthreads();
    }
    float inv = 1.0f / red[0];
    float4 acc = make_float4(0.f, 0.f, 0.f, 0.f);
    for (int j = rs; j < re; j++) {
        int s = g_csr[j];
        float w = __expf(lrelu(g_ssrc[s] + sdv) - m) * inv;
        float4 xv = ((const float4*)(x + (size_t)s * F0))[tid];
        acc.x += w * xv.x; acc.y += w * xv.y;
        acc.z += w * xv.z; acc.w += w * xv.w;
    }
    ((float4*)(g_agg1 + (size_t)n * F0))[tid] = acc;
}

__global__ void k_gat2(const float* __restrict__ b2) {
    int n = blockIdx.x, tid = threadIdx.x;   // 256 threads
    int rs = g_off[n], re = g_off[n + 1];
    float sdv = g_sdst[n];
    __shared__ float red[256];
    float m = -1e30f;
    for (int j = rs + tid; j < re; j += 256)
        m = fmaxf(m, lrelu(g_ssrc[g_csr[j]] + sdv));
    red[tid] = m; __syncthreads();
    for (int s = 128; s > 0; s >>= 1) {
        if (tid < s) red[tid] = fmaxf(red[tid], red[tid + s]);
        __syncthreads();
    }
    m = red[0]; __syncthreads();
    float den = 0.f;
    for (int j = rs + tid; j < re; j += 256)
        den += __expf(lrelu(g_ssrc[g_csr[j]] + sdv) - m);
    red[tid] = den; __syncthreads();
    for (int s = 128; s > 0; s >>= 1) {
        if (tid < s) red[tid] += red[tid + s];
        __syncthreads();
    }
    float inv = 1.0f / red[0];
    float4 acc = make_float4(0.f, 0.f, 0.f, 0.f);
    for (int j = rs; j < re; j++) {
        int s = g_csr[j];
        float w = __expf(lrelu(g_ssrc[s] + sdv) - m) * inv;
        float4 hv = ((const float4*)(g_h2 + (size_t)s * F2))[tid];
        acc.x += w * hv.x; acc.y += w * hv.y;
        acc.z += w * hv.z; acc.w += w * hv.w;
    }
    float4 bv = ((const float4*)b2)[tid];
    acc.x = fmaxf(acc.x + bv.x, 0.f);
    acc.y = fmaxf(acc.y + bv.y, 0.f);
    acc.z = fmaxf(acc.z + bv.z, 0.f);
    acc.w = fmaxf(acc.w + bv.w, 0.f);
    ((float4*)(g_agg2 + (size_t)n * F2))[tid] = acc;
}

// ---------------- layer 3: tiny GEMM then fused gather + log_softmax ----------------
__global__ void k_gemm3(const float* __restrict__ W3) {
    int node = blockIdx.x;
    int warp = threadIdx.x >> 5;   // 0..6
    int lane = threadIdx.x & 31;
    const float* a = g_agg2 + (size_t)node * F2;
    float s = 0.f;
    for (int k = lane; k < F2; k += 32) s += a[k] * W3[k * F3 + warp];
    #pragma unroll
    for (int o = 16; o > 0; o >>= 1) s += __shfl_down_sync(0xffffffff, s, o);
    if (lane == 0) g_h3[node * F3 + warp] = s;
}

__global__ void k_gat3f(const float* __restrict__ b3, float* __restrict__ out) {
    int wg = (blockIdx.x * blockDim.x + threadIdx.x) >> 5;
    if (wg >= NN) return;
    int lane = threadIdx.x & 31;
    int rs = g_off[wg], re = g_off[wg + 1];
    float sdv = g_sdst[wg];
    float m = -1e30f;
    for (int j = rs + lane; j < re; j += 32)
        m = fmaxf(m, lrelu(g_ssrc[g_csr[j]] + sdv));
    #pragma unroll
    for (int o = 16; o > 0; o >>= 1) m = fmaxf(m, __shfl_xor_sync(0xffffffff, m, o));
    float den = 0.f;
    for (int j = rs + lane; j < re; j += 32)
        den += __expf(lrelu(g_ssrc[g_csr[j]] + sdv) - m);
    #pragma unroll
    for (int o = 16; o > 0; o >>= 1) den += __shfl_xor_sync(0xffffffff, den, o);
    float inv = 1.0f / den;
    float acc = 0.f;
    for (int j = rs; j < re; j++) {
        int s = g_csr[j];
        float w = __expf(lrelu(g_ssrc[s] + sdv) - m) * inv;
        if (lane < F3) acc += w * g_h3[s * F3 + lane];
    }
    float z = (lane < F3) ? acc + b3[lane] : -1e30f;
    float mz = z;
    #pragma unroll
    for (int o = 16; o > 0; o >>= 1) mz = fmaxf(mz, __shfl_xor_sync(0xffffffff, mz, o));
    float e = (lane < F3) ? expf(z - mz) : 0.f;
    #pragma unroll
    for (int o = 16; o > 0; o >>= 1) e += __shfl_xor_sync(0xffffffff, e, o);
    float l = mz + logf(e);
    if (lane < F3) out[wg * F3 + lane] = z - l;
}

// ---------------- tf32 mma.sync GEMM, cp.async pipelined, BK=64 ----------------
// C[M,Nc] = A[M,K] @ B[K,Nc]. BM=128, BN=256, BK=64, 512 threads (16 warps, 4x4).
// Warp tile 32x64 = 2 m16 x 8 n8 of m16n8k8; 8 ks-steps per k-tile.
// SMEM A: [m][k] stride 68 words (frag banks 4g+c clean).
// SMEM B: [k][n] stride 264 words (frag banks 8c+g clean).
#define SA_STR 68
#define SB_STR 264
#define ST_A (128 * SA_STR)          // 8704 words
#define ST_B (64 * SB_STR)           // 16896 words
#define ST_WORDS (ST_A + ST_B)       // 25600 words per stage
#define SM_BYTES (2 * ST_WORDS * 4)  // 204800 bytes

__device__ __forceinline__ void g_fill_async(const float* __restrict__ A,
                                             const float* __restrict__ B,
                                             uint32_t sa_u, uint32_t sb_u,
                                             int row0, int col0, int kt,
                                             int M, int Nc, int K, int tid) {
    #pragma unroll
    for (int i = 0; i < 4; i++) {          // A: 128x64 = 2048 float4 / 512 thr
        int idx = i * 512 + tid;
        int m = idx >> 4, k4 = idx & 15;
        int gr = row0 + m;
        int ok = gr < M;
        const float* src = A + (size_t)(ok ? gr : row0) * K + kt * 64 + k4 * 4;
        cpa16(sa_u + (uint32_t)(m * SA_STR + k4 * 4) * 4, src, ok ? 16 : 0);
    }
    #pragma unroll
    for (int i = 0; i < 8; i++) {          // B: 64x256 = 4096 float4 / 512 thr
        int idx = i * 512 + tid;
        int k = idx >> 6, n4 = idx & 63;
        const float* src = B + (size_t)(kt * 64 + k) * Nc + col0 + n4 * 4;
        cpa16(sb_u + (uint32_t)(k * SB_STR + n4 * 4) * 4, src, 16);
    }
    asm volatile("cp.async.commit_group;" ::: "memory");
}

__global__ void __launch_bounds__(512, 1)
tc_gemm(const float* __restrict__ A, const float* __restrict__ B, float* __restrict__ C,
        int M, int Nc, int K, const float* __restrict__ bias, int doRelu) {
    extern __shared__ float sm[];
    uint32_t smu = smem_u32(sm);
    int tid = threadIdx.x;
    int lane = tid & 31, wid = tid >> 5;
    int warp_m = wid & 3, warp_n = wid >> 2;   // 4 x 4
    int g = lane >> 2, c = lane & 3;
    int row0 = blockIdx.y * 128, col0 = blockIdx.x * 256;

    const uint32_t A_off[2] = { 0u, (uint32_t)ST_WORDS };
    const uint32_t B_off[2] = { (uint32_t)ST_A, (uint32_t)(ST_WORDS + ST_A) };

    float acc[2][8][4];
    #pragma unroll
    for (int t = 0; t < 2; t++)
        #pragma unroll
        for (int u = 0; u < 8; u++)
            #pragma unroll
            for (int j = 0; j < 4; j++) acc[t][u][j] = 0.f;

    const int KT = K >> 6;
    g_fill_async(A, B, smu + A_off[0] * 4, smu + B_off[0] * 4, row0, col0, 0, M, Nc, K, tid);

    for (int kt = 0; kt < KT; kt++) {
        int buf = kt & 1;
        if (kt + 1 < KT) {
            g_fill_async(A, B, smu + A_off[buf ^ 1] * 4, smu + B_off[buf ^ 1] * 4,
                         row0, col0, kt + 1, M, Nc, K, tid);
            asm volatile("cp.async.wait_group 1;" ::: "memory");
        } else {
            asm volatile("cp.async.wait_group 0;" ::: "memory");
        }
        __syncthreads();
        const float* sa = sm + A_off[buf];
        const float* sb = sm + B_off[buf];
        #pragma unroll
        for (int ks = 0; ks < 8; ks++) {
            uint32_t af[2][4];
            #pragma unroll
            for (int t = 0; t < 2; t++) {
                const float* pa = sa + (warp_m * 32 + t * 16 + g) * SA_STR + ks * 8 + c;
                af[t][0] = tf32r(pa[0]);
                af[t][1] = tf32r(pa[8 * SA_STR]);
                af[t][2] = tf32r(pa[4]);
                af[t][3] = tf32r(pa[8 * SA_STR + 4]);
            }
            uint32_t bf[8][2];
            #pragma unroll
            for (int u = 0; u < 8; u++) {
                const float* pb = sb + (ks * 8 + c) * SB_STR + warp_n * 64 + u * 8 + g;
                bf[u][0] = tf32r(pb[0]);
                bf[u][1] = tf32r(pb[4 * SB_STR]);
            }
            #pragma unroll
            for (int t = 0; t < 2; t++)
                #pragma unroll
                for (int u = 0; u < 8; u++)
                    mma8(acc[t][u], af[t], bf[u]);
        }
        __syncthreads();
    }

    // epilogue
    #pragma unroll
    for (int t = 0; t < 2; t++) {
        int r0 = row0 + warp_m * 32 + t * 16 + g;
        #pragma unroll
        for (int u = 0; u < 8; u++) {
            int cc = col0 + warp_n * 64 + u * 8 + 2 * c;
            float2 v0 = make_float2(acc[t][u][0], acc[t][u][1]);
            float2 v1 = make_float2(acc[t][u][2], acc[t][u][3]);
            if (bias) {
                float b0v = bias[cc], b1v = bias[cc + 1];
                v0.x += b0v; v0.y += b1v;
                v1.x += b0v; v1.y += b1v;
            }
            if (doRelu) {
                v0.x = fmaxf(v0.x, 0.f); v0.y = fmaxf(v0.y, 0.f);
                v1.x = fmaxf(v1.x, 0.f); v1.y = fmaxf(v1.y, 0.f);
            }
            if (r0 < M)     *(float2*)(C + (size_t)r0 * Nc + cc) = v0;
            if (r0 + 8 < M) *(float2*)(C + (size_t)(r0 + 8) * Nc + cc) = v1;
        }
    }
}

// ---------------- launch ----------------
extern "C" void kernel_launch(void* const* d_in, const int* in_sizes, int n_in,
                              void* d_out, int out_size) {
    const float* x   = (const float*)d_in[0];
    const int*   ei  = (const int*)d_in[1];
    const float* W1  = (const float*)d_in[2];
    const float* as1 = (const float*)d_in[3];
    const float* ad1 = (const float*)d_in[4];
    const float* b1  = (const float*)d_in[5];
    const float* W2  = (const float*)d_in[6];
    const float* as2 = (const float*)d_in[7];
    const float* ad2 = (const float*)d_in[8];
    const float* b2  = (const float*)d_in[9];
    const float* W3  = (const float*)d_in[10];
    const float* as3 = (const float*)d_in[11];
    const float* ad3 = (const float*)d_in[12];
    const float* b3  = (const float*)d_in[13];
    float* out = (float*)d_out;

    void *p_agg1, *p_agg2, *p_h1, *p_h2, *p_h3, *p_v1s, *p_v1d;
    cudaGetSymbolAddress(&p_agg1, g_agg1);
    cudaGetSymbolAddress(&p_agg2, g_agg2);
    cudaGetSymbolAddress(&p_h1, g_h1);
    cudaGetSymbolAddress(&p_h2, g_h2);
    cudaGetSymbolAddress(&p_h3, g_h3);
    cudaGetSymbolAddress(&p_v1s, g_v1s);
    cudaGetSymbolAddress(&p_v1d, g_v1d);

    cudaFuncSetAttribute(tc_gemm, cudaFuncAttributeMaxDynamicSharedMemorySize, SM_BYTES);

    const int EB = (EE + 255) / 256;
    const int MB = (NN + 127) / 128;

    // ---- CSR build (reused by all 3 layers) ----
    k_zerodeg<<<(NN + 255) / 256, 256>>>();
    k_deg<<<EB, 256>>>(ei);
    k_scan<<<1, 1024>>>();
    k_fill<<<EB, 256>>>(ei);

    // ---- Layer 1: scores on x, gather in x-space (512), then GEMM ----
    k_v1<<<F0, 256>>>(W1, as1, ad1);
    k_scores<<<NN, 128>>>(x, (const float*)p_v1s, (const float*)p_v1d, F0);
    k_gat1<<<NN, 128>>>(x);
    {
        dim3 grd(F1 / 256, MB);
        tc_gemm<<<grd, 512, SM_BYTES>>>((const float*)p_agg1, W1, (float*)p_h1,
                                        NN, F1, F0, b1, 1);
    }

    // ---- Layer 2: GEMM (4096->1024), scores, gather (+bias+relu fused) ----
    {
        dim3 grd(F2 / 256, MB);
        tc_gemm<<<grd, 512, SM_BYTES>>>((const float*)p_h1, W2, (float*)p_h2,
                                        NN, F2, F1, nullptr, 0);
    }
    k_scores<<<NN, 128>>>((const float*)p_h2, as2, ad2, F2);
    k_gat2<<<NN, 256>>>(b2);

    // ---- Layer 3: tiny GEMM (1024->7), scores, fused gather+log_softmax ----
    k_gemm3<<<NN, 224>>>(W3);
    k_scores<<<NN, 128>>>((const float*)p_h3, as3, ad3, F3);
    k_gat3f<<<(NN * 32 + 255) / 256, 256>>>(b3, out);
}

// round 7
// speedup vs baseline: 5.6174x; 1.0890x over previous
#include <cuda_runtime.h>
#include <math.h>
#include <stdint.h>

#define NN 10000
#define E0 80000
#define EE 90000
#define F0 512
#define F1 4096
#define F2 1024
#define F3 7
#define NSLOPE 0.2f

// ---------------- scratch (static device globals; no allocation) ----------------
__device__ float g_agg1[(size_t)NN * F0];
__device__ float g_h1[(size_t)NN * F1];
__device__ float g_h2[(size_t)NN * F2];
__device__ float g_agg2[(size_t)NN * F2];
__device__ float g_h3[NN * F3];
__device__ float g_ssrc[NN], g_sdst[NN];
__device__ float g_v1s[F0], g_v1d[F0];
__device__ float g_w1c[(size_t)F0 * F1];   // tf32-rounded W1
__device__ float g_w2c[(size_t)F1 * F2];   // tf32-rounded W2
// CSR by destination
__device__ int g_deg[NN];
__device__ int g_cursor[NN];
__device__ int g_off[NN + 1];
__device__ int g_csr[EE];

__device__ __forceinline__ void edge_sd(const int* __restrict__ ei, int e, int& s, int& d) {
    if (e < E0) { s = ei[e]; d = ei[E0 + e]; }
    else        { s = e - E0; d = e - E0; }
}
__device__ __forceinline__ uint32_t tf32r(float x) {
    uint32_t t;
    asm("cvt.rna.tf32.f32 %0, %1;" : "=r"(t) : "f"(x));
    return t;
}
__device__ __forceinline__ float tf32f(float x) { return __uint_as_float(tf32r(x)); }
__device__ __forceinline__ uint32_t smem_u32(const void* p) {
    uint32_t a;
    asm("{ .reg .u64 t; cvta.to.shared.u64 t, %1; cvt.u32.u64 %0, t; }" : "=r"(a) : "l"(p));
    return a;
}
__device__ __forceinline__ void cpa16(uint32_t dst, const void* src, int sz) {
    asm volatile("cp.async.cg.shared.global [%0], [%1], 16, %2;"
                 :: "r"(dst), "l"(src), "r"(sz));
}
__device__ __forceinline__ void mma8(float* c, const uint32_t* a, const uint32_t* b) {
    asm volatile(
        "mma.sync.aligned.m16n8k8.row.col.f32.tf32.tf32.f32 "
        "{%0,%1,%2,%3}, {%4,%5,%6,%7}, {%8,%9}, {%0,%1,%2,%3};"
        : "+f"(c[0]), "+f"(c[1]), "+f"(c[2]), "+f"(c[3])
        : "r"(a[0]), "r"(a[1]), "r"(a[2]), "r"(a[3]), "r"(b[0]), "r"(b[1]));
}
__device__ __forceinline__ float lrelu(float v) { return (v > 0.f) ? v : NSLOPE * v; }

// ---------------- weight pre-conversion to tf32 ----------------
__global__ void k_cvtw(const float* __restrict__ in, float* __restrict__ out, long n4) {
    long i0 = (long)blockIdx.x * blockDim.x + threadIdx.x;
    long stride = (long)gridDim.x * blockDim.x;
    for (long i = i0; i < n4; i += stride) {
        float4 v = ((const float4*)in)[i];
        v.x = tf32f(v.x); v.y = tf32f(v.y);
        v.z = tf32f(v.z); v.w = tf32f(v.w);
        ((float4*)out)[i] = v;
    }
}

// ---------------- CSR build ----------------
__global__ void k_zerodeg() {
    int i = blockIdx.x * blockDim.x + threadIdx.x;
    if (i < NN) g_deg[i] = 0;
}
__global__ void k_deg(const int* __restrict__ ei) {
    int e = blockIdx.x * blockDim.x + threadIdx.x;
    if (e >= EE) return;
    int s, d; edge_sd(ei, e, s, d);
    atomicAdd(&g_deg[d], 1);
}
__global__ void k_scan() {   // single block, 1024 threads, chunk=10
    __shared__ int sh[1024];
    int tid = threadIdx.x;
    int base = tid * 10;
    int cnt[10]; int local = 0;
    #pragma unroll
    for (int i = 0; i < 10; i++) {
        int idx = base + i;
        int c = (idx < NN) ? g_deg[idx] : 0;
        cnt[i] = local; local += c;
    }
    sh[tid] = local;
    __syncthreads();
    for (int off = 1; off < 1024; off <<= 1) {
        int v = (tid >= off) ? sh[tid - off] : 0;
        __syncthreads();
        sh[tid] += v;
        __syncthreads();
    }
    int start = sh[tid] - local;
    #pragma unroll
    for (int i = 0; i < 10; i++) {
        int idx = base + i;
        if (idx < NN) { g_off[idx] = start + cnt[i]; g_cursor[idx] = 0; }
    }
    if (tid == 1023) g_off[NN] = sh[1023];
}
__global__ void k_fill(const int* __restrict__ ei) {
    int e = blockIdx.x * blockDim.x + threadIdx.x;
    if (e >= EE) return;
    int s, d; edge_sd(ei, e, s, d);
    int p = atomicAdd(&g_cursor[d], 1);
    g_csr[g_off[d] + p] = s;
}

// ---------------- attention-vector & node-score kernels ----------------
__global__ void k_v1(const float* __restrict__ W1, const float* __restrict__ as,
                     const float* __restrict__ ad) {
    int r = blockIdx.x;
    int tid = threadIdx.x;
    float ss = 0.f, sd = 0.f;
    const float* wrow = W1 + (size_t)r * F1;
    for (int j = tid; j < F1; j += 256) {
        float w = wrow[j];
        ss += w * as[j];
        sd += w * ad[j];
    }
    __shared__ float s1[256], s2[256];
    s1[tid] = ss; s2[tid] = sd;
    __syncthreads();
    for (int s = 128; s > 0; s >>= 1) {
        if (tid < s) { s1[tid] += s1[tid + s]; s2[tid] += s2[tid + s]; }
        __syncthreads();
    }
    if (tid == 0) { g_v1s[r] = s1[0]; g_v1d[r] = s2[0]; }
}

__global__ void k_scores(const float* __restrict__ X, const float* __restrict__ vs,
                         const float* __restrict__ vd, int F) {
    int node = blockIdx.x;
    int tid = threadIdx.x;      // 128
    const float* xr = X + (size_t)node * F;
    float ss = 0.f, sd = 0.f;
    for (int j = tid; j < F; j += 128) {
        float x = xr[j];
        ss += x * vs[j];
        sd += x * vd[j];
    }
    __shared__ float s1[128], s2[128];
    s1[tid] = ss; s2[tid] = sd;
    __syncthreads();
    for (int s = 64; s > 0; s >>= 1) {
        if (tid < s) { s1[tid] += s1[tid + s]; s2[tid] += s2[tid + s]; }
        __syncthreads();
    }
    if (tid == 0) { g_ssrc[node] = s1[0]; g_sdst[node] = s2[0]; }
}

// ---------------- gather aggregation (softmax fused, no atomics) ----------------
__global__ void k_gat1(const float* __restrict__ x) {
    int n = blockIdx.x, tid = threadIdx.x;   // 128 threads
    int rs = g_off[n], re = g_off[n + 1];
    float sdv = g_sdst[n];
    __shared__ float red[128];
    float m = -1e30f;
    for (int j = rs + tid; j < re; j += 128)
        m = fmaxf(m, lrelu(g_ssrc[g_csr[j]] + sdv));
    red[tid] = m; __syncthreads();
    for (int s = 64; s > 0; s >>= 1) {
        if (tid < s) red[tid] = fmaxf(red[tid], red[tid + s]);
        __syncthreads();
    }
    m = red[0]; __syncthreads();
    float den = 0.f;
    for (int j = rs + tid; j < re; j += 128)
        den += __expf(lrelu(g_ssrc[g_csr[j]] + sdv) - m);
    red[tid] = den; __syncthreads();
    for (int s = 64; s > 0; s >>= 1) {
        if (tid < s) red[tid] += red[tid + s];
        __syncthreads();
    }
    float inv = 1.0f / red[0];
    float4 acc = make_float4(0.f, 0.f, 0.f, 0.f);
    for (int j = rs; j < re; j++) {
        int s = g_csr[j];
        float w = __expf(lrelu(g_ssrc[s] + sdv) - m) * inv;
        float4 xv = ((const float4*)(x + (size_t)s * F0))[tid];
        acc.x += w * xv.x; acc.y += w * xv.y;
        acc.z += w * xv.z; acc.w += w * xv.w;
    }
    // store tf32-rounded: agg1 only feeds GEMM1's A operand (same bits as cvt-at-load)
    acc.x = tf32f(acc.x); acc.y = tf32f(acc.y);
    acc.z = tf32f(acc.z); acc.w = tf32f(acc.w);
    ((float4*)(g_agg1 + (size_t)n * F0))[tid] = acc;
}

__global__ void k_gat2(const float* __restrict__ b2) {
    int n = blockIdx.x, tid = threadIdx.x;   // 256 threads
    int rs = g_off[n], re = g_off[n + 1];
    float sdv = g_sdst[n];
    __shared__ float red[256];
    float m = -1e30f;
    for (int j = rs + tid; j < re; j += 256)
        m = fmaxf(m, lrelu(g_ssrc[g_csr[j]] + sdv));
    red[tid] = m; __syncthreads();
    for (int s = 128; s > 0; s >>= 1) {
        if (tid < s) red[tid] = fmaxf(red[tid], red[tid + s]);
        __syncthreads();
    }
    m = red[0]; __syncthreads();
    float den = 0.f;
    for (int j = rs + tid; j < re; j += 256)
        den += __expf(lrelu(g_ssrc[g_csr[j]] + sdv) - m);
    red[tid] = den; __syncthreads();
    for (int s = 128; s > 0; s >>= 1) {
        if (tid < s) red[tid] += red[tid + s];
        __syncthreads();
    }
    float inv = 1.0f / red[0];
    float4 acc = make_float4(0.f, 0.f, 0.f, 0.f);
    for (int j = rs; j < re; j++) {
        int s = g_csr[j];
        float w = __expf(lrelu(g_ssrc[s] + sdv) - m) * inv;
        float4 hv = ((const float4*)(g_h2 + (size_t)s * F2))[tid];
        acc.x += w * hv.x; acc.y += w * hv.y;
        acc.z += w * hv.z; acc.w += w * hv.w;
    }
    float4 bv = ((const float4*)b2)[tid];
    acc.x = fmaxf(acc.x + bv.x, 0.f);
    acc.y = fmaxf(acc.y + bv.y, 0.f);
    acc.z = fmaxf(acc.z + bv.z, 0.f);
    acc.w = fmaxf(acc.w + bv.w, 0.f);
    ((float4*)(g_agg2 + (size_t)n * F2))[tid] = acc;
}

// ---------------- layer 3: tiny GEMM then fused gather + log_softmax ----------------
__global__ void k_gemm3(const float* __restrict__ W3) {
    int node = blockIdx.x;
    int warp = threadIdx.x >> 5;   // 0..6
    int lane = threadIdx.x & 31;
    const float* a = g_agg2 + (size_t)node * F2;
    float s = 0.f;
    for (int k = lane; k < F2; k += 32) s += a[k] * W3[k * F3 + warp];
    #pragma unroll
    for (int o = 16; o > 0; o >>= 1) s += __shfl_down_sync(0xffffffff, s, o);
    if (lane == 0) g_h3[node * F3 + warp] = s;
}

__global__ void k_gat3f(const float* __restrict__ b3, float* __restrict__ out) {
    int wg = (blockIdx.x * blockDim.x + threadIdx.x) >> 5;
    if (wg >= NN) return;
    int lane = threadIdx.x & 31;
    int rs = g_off[wg], re = g_off[wg + 1];
    float sdv = g_sdst[wg];
    float m = -1e30f;
    for (int j = rs + lane; j < re; j += 32)
        m = fmaxf(m, lrelu(g_ssrc[g_csr[j]] + sdv));
    #pragma unroll
    for (int o = 16; o > 0; o >>= 1) m = fmaxf(m, __shfl_xor_sync(0xffffffff, m, o));
    float den = 0.f;
    for (int j = rs + lane; j < re; j += 32)
        den += __expf(lrelu(g_ssrc[g_csr[j]] + sdv) - m);
    #pragma unroll
    for (int o = 16; o > 0; o >>= 1) den += __shfl_xor_sync(0xffffffff, den, o);
    float inv = 1.0f / den;
    float acc = 0.f;
    for (int j = rs; j < re; j++) {
        int s = g_csr[j];
        float w = __expf(lrelu(g_ssrc[s] + sdv) - m) * inv;
        if (lane < F3) acc += w * g_h3[s * F3 + lane];
    }
    float z = (lane < F3) ? acc + b3[lane] : -1e30f;
    float mz = z;
    #pragma unroll
    for (int o = 16; o > 0; o >>= 1) mz = fmaxf(mz, __shfl_xor_sync(0xffffffff, mz, o));
    float e = (lane < F3) ? expf(z - mz) : 0.f;
    #pragma unroll
    for (int o = 16; o > 0; o >>= 1) e += __shfl_xor_sync(0xffffffff, e, o);
    float l = mz + logf(e);
    if (lane < F3) out[wg * F3 + lane] = z - l;
}

// ---------------- tf32 mma.sync GEMM, cp.async pipelined, BK=64 ----------------
// Operands are pre-rounded to tf32 in gmem -> mainloop is pure LDS + HMMA (no CVT).
// C[M,Nc] = A[M,K] @ B[K,Nc]. BM=128, BN=256, BK=64, 512 threads (16 warps, 4x4).
// Warp tile 32x64 = 2 m16 x 8 n8 of m16n8k8; 8 ks-steps per k-tile.
// SMEM A: [m][k] stride 68 words (frag banks 4g+c clean).
// SMEM B: [k][n] stride 264 words (frag banks 8c+g clean).
#define SA_STR 68
#define SB_STR 264
#define ST_A (128 * SA_STR)          // 8704 words
#define ST_B (64 * SB_STR)           // 16896 words
#define ST_WORDS (ST_A + ST_B)       // 25600 words per stage
#define SM_BYTES (2 * ST_WORDS * 4)  // 204800 bytes

__device__ __forceinline__ void g_fill_async(const float* __restrict__ A,
                                             const float* __restrict__ B,
                                             uint32_t sa_u, uint32_t sb_u,
                                             int row0, int col0, int kt,
                                             int M, int Nc, int K, int tid) {
    #pragma unroll
    for (int i = 0; i < 4; i++) {          // A: 128x64 = 2048 float4 / 512 thr
        int idx = i * 512 + tid;
        int m = idx >> 4, k4 = idx & 15;
        int gr = row0 + m;
        int ok = gr < M;
        const float* src = A + (size_t)(ok ? gr : row0) * K + kt * 64 + k4 * 4;
        cpa16(sa_u + (uint32_t)(m * SA_STR + k4 * 4) * 4, src, ok ? 16 : 0);
    }
    #pragma unroll
    for (int i = 0; i < 8; i++) {          // B: 64x256 = 4096 float4 / 512 thr
        int idx = i * 512 + tid;
        int k = idx >> 6, n4 = idx & 63;
        const float* src = B + (size_t)(kt * 64 + k) * Nc + col0 + n4 * 4;
        cpa16(sb_u + (uint32_t)(k * SB_STR + n4 * 4) * 4, src, 16);
    }
    asm volatile("cp.async.commit_group;" ::: "memory");
}

__global__ void __launch_bounds__(512, 1)
tc_gemm(const float* __restrict__ A, const float* __restrict__ B, float* __restrict__ C,
        int M, int Nc, int K, const float* __restrict__ bias, int doRelu, int cvtOut) {
    extern __shared__ float sm[];
    uint32_t smu = smem_u32(sm);
    int tid = threadIdx.x;
    int lane = tid & 31, wid = tid >> 5;
    int warp_m = wid & 3, warp_n = wid >> 2;   // 4 x 4
    int g = lane >> 2, c = lane & 3;
    int row0 = blockIdx.y * 128, col0 = blockIdx.x * 256;

    const uint32_t A_off[2] = { 0u, (uint32_t)ST_WORDS };
    const uint32_t B_off[2] = { (uint32_t)ST_A, (uint32_t)(ST_WORDS + ST_A) };

    float acc[2][8][4];
    #pragma unroll
    for (int t = 0; t < 2; t++)
        #pragma unroll
        for (int u = 0; u < 8; u++)
            #pragma unroll
            for (int j = 0; j < 4; j++) acc[t][u][j] = 0.f;

    const int KT = K >> 6;
    g_fill_async(A, B, smu + A_off[0] * 4, smu + B_off[0] * 4, row0, col0, 0, M, Nc, K, tid);

    for (int kt = 0; kt < KT; kt++) {
        int buf = kt & 1;
        if (kt + 1 < KT) {
            g_fill_async(A, B, smu + A_off[buf ^ 1] * 4, smu + B_off[buf ^ 1] * 4,
                         row0, col0, kt + 1, M, Nc, K, tid);
            asm volatile("cp.async.wait_group 1;" ::: "memory");
        } else {
            asm volatile("cp.async.wait_group 0;" ::: "memory");
        }
        __syncthreads();
        const float* sa = sm + A_off[buf];
        const float* sb = sm + B_off[buf];
        #pragma unroll
        for (int ks = 0; ks < 8; ks++) {
            uint32_t af[2][4];
            #pragma unroll
            for (int t = 0; t < 2; t++) {
                const float* pa = sa + (warp_m * 32 + t * 16 + g) * SA_STR + ks * 8 + c;
                af[t][0] = __float_as_uint(pa[0]);
                af[t][1] = __float_as_uint(pa[8 * SA_STR]);
                af[t][2] = __float_as_uint(pa[4]);
                af[t][3] = __float_as_uint(pa[8 * SA_STR + 4]);
            }
            uint32_t bf[8][2];
            #pragma unroll
            for (int u = 0; u < 8; u++) {
                const float* pb = sb + (ks * 8 + c) * SB_STR + warp_n * 64 + u * 8 + g;
                bf[u][0] = __float_as_uint(pb[0]);
                bf[u][1] = __float_as_uint(pb[4 * SB_STR]);
            }
            #pragma unroll
            for (int t = 0; t < 2; t++)
                #pragma unroll
                for (int u = 0; u < 8; u++)
                    mma8(acc[t][u], af[t], bf[u]);
        }
        __syncthreads();
    }

    // epilogue
    #pragma unroll
    for (int t = 0; t < 2; t++) {
        int r0 = row0 + warp_m * 32 + t * 16 + g;
        #pragma unroll
        for (int u = 0; u < 8; u++) {
            int cc = col0 + warp_n * 64 + u * 8 + 2 * c;
            float2 v0 = make_float2(acc[t][u][0], acc[t][u][1]);
            float2 v1 = make_float2(acc[t][u][2], acc[t][u][3]);
            if (bias) {
                float b0v = bias[cc], b1v = bias[cc + 1];
                v0.x += b0v; v0.y += b1v;
                v1.x += b0v; v1.y += b1v;
            }
            if (doRelu) {
                v0.x = fmaxf(v0.x, 0.f); v0.y = fmaxf(v0.y, 0.f);
                v1.x = fmaxf(v1.x, 0.f); v1.y = fmaxf(v1.y, 0.f);
            }
            if (cvtOut) {
                v0.x = tf32f(v0.x); v0.y = tf32f(v0.y);
                v1.x = tf32f(v1.x); v1.y = tf32f(v1.y);
            }
            if (r0 < M)     *(float2*)(C + (size_t)r0 * Nc + cc) = v0;
            if (r0 + 8 < M) *(float2*)(C + (size_t)(r0 + 8) * Nc + cc) = v1;
        }
    }
}

// ---------------- launch ----------------
extern "C" void kernel_launch(void* const* d_in, const int* in_sizes, int n_in,
                              void* d_out, int out_size) {
    const float* x   = (const float*)d_in[0];
    const int*   ei  = (const int*)d_in[1];
    const float* W1  = (const float*)d_in[2];
    const float* as1 = (const float*)d_in[3];
    const float* ad1 = (const float*)d_in[4];
    const float* b1  = (const float*)d_in[5];
    const float* W2  = (const float*)d_in[6];
    const float* as2 = (const float*)d_in[7];
    const float* ad2 = (const float*)d_in[8];
    const float* b2  = (const float*)d_in[9];
    const float* W3  = (const float*)d_in[10];
    const float* as3 = (const float*)d_in[11];
    const float* ad3 = (const float*)d_in[12];
    const float* b3  = (const float*)d_in[13];
    float* out = (float*)d_out;

    void *p_agg1, *p_agg2, *p_h1, *p_h2, *p_h3, *p_v1s, *p_v1d, *p_w1c, *p_w2c;
    cudaGetSymbolAddress(&p_agg1, g_agg1);
    cudaGetSymbolAddress(&p_agg2, g_agg2);
    cudaGetSymbolAddress(&p_h1, g_h1);
    cudaGetSymbolAddress(&p_h2, g_h2);
    cudaGetSymbolAddress(&p_h3, g_h3);
    cudaGetSymbolAddress(&p_v1s, g_v1s);
    cudaGetSymbolAddress(&p_v1d, g_v1d);
    cudaGetSymbolAddress(&p_w1c, g_w1c);
    cudaGetSymbolAddress(&p_w2c, g_w2c);

    cudaFuncSetAttribute(tc_gemm, cudaFuncAttributeMaxDynamicSharedMemorySize, SM_BYTES);

    const int EB = (EE + 255) / 256;
    const int MB = (NN + 127) / 128;

    // ---- weight pre-conversion (independent of everything else) ----
    k_cvtw<<<1024, 256>>>(W1, (float*)p_w1c, (long)F0 * F1 / 4);
    k_cvtw<<<2048, 256>>>(W2, (float*)p_w2c, (long)F1 * F2 / 4);

    // ---- CSR build (reused by all 3 layers) ----
    k_zerodeg<<<(NN + 255) / 256, 256>>>();
    k_deg<<<EB, 256>>>(ei);
    k_scan<<<1, 1024>>>();
    k_fill<<<EB, 256>>>(ei);

    // ---- Layer 1: scores on x, gather in x-space (512), then GEMM ----
    k_v1<<<F0, 256>>>(W1, as1, ad1);
    k_scores<<<NN, 128>>>(x, (const float*)p_v1s, (const float*)p_v1d, F0);
    k_gat1<<<NN, 128>>>(x);
    {
        dim3 grd(F1 / 256, MB);
        tc_gemm<<<grd, 512, SM_BYTES>>>((const float*)p_agg1, (const float*)p_w1c,
                                        (float*)p_h1, NN, F1, F0, b1, 1, 1);
    }

    // ---- Layer 2: GEMM (4096->1024), scores, gather (+bias+relu fused) ----
    {
        dim3 grd(F2 / 256, MB);
        tc_gemm<<<grd, 512, SM_BYTES>>>((const float*)p_h1, (const float*)p_w2c,
                                        (float*)p_h2, NN, F2, F1, nullptr, 0, 0);
    }
    k_scores<<<NN, 128>>>((const float*)p_h2, as2, ad2, F2);
    k_gat2<<<NN, 256>>>(b2);

    // ---- Layer 3: tiny GEMM (1024->7), scores, fused gather+log_softmax ----
    k_gemm3<<<NN, 224>>>(W3);
    k_scores<<<NN, 128>>>((const float*)p_h3, as3, ad3, F3);
    k_gat3f<<<(NN * 32 + 255) / 256, 256>>>(b3, out);
}

// round 9
// speedup vs baseline: 8.4915x; 1.5116x over previous
#include <cuda_runtime.h>
#include <cuda_fp16.h>
#include <math.h>
#include <stdint.h>

#define NN 10000
#define E0 80000
#define EE 90000
#define F0 512
#define F1 4096
#define F2 1024
#define F3 7
#define NSLOPE 0.2f

// ---------------- scratch (static device globals; no allocation) ----------------
__device__ __half g_agg1h[(size_t)NN * F0];     // half agg (A of GEMM1)
__device__ __half g_h1h[(size_t)NN * F1];       // half h1 (A of GEMM2)
__device__ float  g_h2[(size_t)NN * F2];
__device__ float  g_agg2[(size_t)NN * F2];
__device__ float  g_h3[NN * F3];
__device__ float  g_ssrc[NN], g_sdst[NN];
__device__ float  g_v1s[F0], g_v1d[F0];
__device__ __half g_w1t[(size_t)F1 * F0];       // W1^T half [N][K]
__device__ __half g_w2t[(size_t)F2 * F1];       // W2^T half [N][K]
// CSR by destination
__device__ int g_deg[NN];
__device__ int g_cursor[NN];
__device__ int g_off[NN + 1];
__device__ int g_csr[EE];

__device__ __forceinline__ void edge_sd(const int* __restrict__ ei, int e, int& s, int& d) {
    if (e < E0) { s = ei[e]; d = ei[E0 + e]; }
    else        { s = e - E0; d = e - E0; }
}
__device__ __forceinline__ uint32_t smem_u32(const void* p) {
    uint32_t a;
    asm("{ .reg .u64 t; cvta.to.shared.u64 t, %1; cvt.u32.u64 %0, t; }" : "=r"(a) : "l"(p));
    return a;
}
__device__ __forceinline__ void cpa16(uint32_t dst, const void* src, int sz) {
    asm volatile("cp.async.cg.shared.global [%0], [%1], 16, %2;"
                 :: "r"(dst), "l"(src), "r"(sz));
}
// fp16 MMA m16n8k16, fp32 accumulate
__device__ __forceinline__ void mma16(float* c, const uint32_t* a, const uint32_t* b) {
    asm volatile(
        "mma.sync.aligned.m16n8k16.row.col.f32.f16.f16.f32 "
        "{%0,%1,%2,%3}, {%4,%5,%6,%7}, {%8,%9}, {%0,%1,%2,%3};"
        : "+f"(c[0]), "+f"(c[1]), "+f"(c[2]), "+f"(c[3])
        : "r"(a[0]), "r"(a[1]), "r"(a[2]), "r"(a[3]), "r"(b[0]), "r"(b[1]));
}
__device__ __forceinline__ float lrelu(float v) { return (v > 0.f) ? v : NSLOPE * v; }

// ---------------- weight transpose + fp16 convert: out[n][k] = half(in[k][n]) ----------------
__global__ void k_transpose_h(const float* __restrict__ in, __half* __restrict__ out,
                              int K, int N) {
    __shared__ __half tile[32][34];
    int n0 = blockIdx.x * 32, k0 = blockIdx.y * 32;
    int tx = threadIdx.x, ty = threadIdx.y;   // 32 x 8
    #pragma unroll
    for (int i = 0; i < 4; i++) {
        int k = k0 + ty + i * 8;
        tile[ty + i * 8][tx] = __float2half_rn(in[(size_t)k * N + n0 + tx]);
    }
    __syncthreads();
    #pragma unroll
    for (int i = 0; i < 4; i++) {
        int n = n0 + ty + i * 8;
        out[(size_t)n * K + k0 + tx] = tile[tx][ty + i * 8];
    }
}

// ---------------- CSR build ----------------
__global__ void k_zerodeg() {
    int i = blockIdx.x * blockDim.x + threadIdx.x;
    if (i < NN) g_deg[i] = 0;
}
__global__ void k_deg(const int* __restrict__ ei) {
    int e = blockIdx.x * blockDim.x + threadIdx.x;
    if (e >= EE) return;
    int s, d; edge_sd(ei, e, s, d);
    atomicAdd(&g_deg[d], 1);
}
__global__ void k_scan() {   // single block, 1024 threads, chunk=10
    __shared__ int sh[1024];
    int tid = threadIdx.x;
    int base = tid * 10;
    int cnt[10]; int local = 0;
    #pragma unroll
    for (int i = 0; i < 10; i++) {
        int idx = base + i;
        int c = (idx < NN) ? g_deg[idx] : 0;
        cnt[i] = local; local += c;
    }
    sh[tid] = local;
    __syncthreads();
    for (int off = 1; off < 1024; off <<= 1) {
        int v = (tid >= off) ? sh[tid - off] : 0;
        __syncthreads();
        sh[tid] += v;
        __syncthreads();
    }
    int start = sh[tid] - local;
    #pragma unroll
    for (int i = 0; i < 10; i++) {
        int idx = base + i;
        if (idx < NN) { g_off[idx] = start + cnt[i]; g_cursor[idx] = 0; }
    }
    if (tid == 1023) g_off[NN] = sh[1023];
}
__global__ void k_fill(const int* __restrict__ ei) {
    int e = blockIdx.x * blockDim.x + threadIdx.x;
    if (e >= EE) return;
    int s, d; edge_sd(ei, e, s, d);
    int p = atomicAdd(&g_cursor[d], 1);
    g_csr[g_off[d] + p] = s;
}

// ---------------- attention-vector & node-score kernels ----------------
__global__ void k_v1(const float* __restrict__ W1, const float* __restrict__ as,
                     const float* __restrict__ ad) {
    int r = blockIdx.x;
    int tid = threadIdx.x;
    float ss = 0.f, sd = 0.f;
    const float* wrow = W1 + (size_t)r * F1;
    for (int j = tid; j < F1; j += 256) {
        float w = wrow[j];
        ss += w * as[j];
        sd += w * ad[j];
    }
    __shared__ float s1[256], s2[256];
    s1[tid] = ss; s2[tid] = sd;
    __syncthreads();
    for (int s = 128; s > 0; s >>= 1) {
        if (tid < s) { s1[tid] += s1[tid + s]; s2[tid] += s2[tid + s]; }
        __syncthreads();
    }
    if (tid == 0) { g_v1s[r] = s1[0]; g_v1d[r] = s2[0]; }
}

__global__ void k_scores(const float* __restrict__ X, const float* __restrict__ vs,
                         const float* __restrict__ vd, int F) {
    int node = blockIdx.x;
    int tid = threadIdx.x;      // 128
    const float* xr = X + (size_t)node * F;
    float ss = 0.f, sd = 0.f;
    for (int j = tid; j < F; j += 128) {
        float x = xr[j];
        ss += x * vs[j];
        sd += x * vd[j];
    }
    __shared__ float s1[128], s2[128];
    s1[tid] = ss; s2[tid] = sd;
    __syncthreads();
    for (int s = 64; s > 0; s >>= 1) {
        if (tid < s) { s1[tid] += s1[tid + s]; s2[tid] += s2[tid + s]; }
        __syncthreads();
    }
    if (tid == 0) { g_ssrc[node] = s1[0]; g_sdst[node] = s2[0]; }
}

// ---------------- gather aggregation (softmax fused, no atomics) ----------------
__global__ void k_gat1(const float* __restrict__ x) {
    int n = blockIdx.x, tid = threadIdx.x;   // 128 threads
    int rs = g_off[n], re = g_off[n + 1];
    float sdv = g_sdst[n];
    __shared__ float red[128];
    float m = -1e30f;
    for (int j = rs + tid; j < re; j += 128)
        m = fmaxf(m, lrelu(g_ssrc[g_csr[j]] + sdv));
    red[tid] = m; __syncthreads();
    for (int s = 64; s > 0; s >>= 1) {
        if (tid < s) red[tid] = fmaxf(red[tid], red[tid + s]);
        __syncthreads();
    }
    m = red[0]; __syncthreads();
    float den = 0.f;
    for (int j = rs + tid; j < re; j += 128)
        den += __expf(lrelu(g_ssrc[g_csr[j]] + sdv) - m);
    red[tid] = den; __syncthreads();
    for (int s = 64; s > 0; s >>= 1) {
        if (tid < s) red[tid] += red[tid + s];
        __syncthreads();
    }
    float inv = 1.0f / red[0];
    float4 acc = make_float4(0.f, 0.f, 0.f, 0.f);
    for (int j = rs; j < re; j++) {
        int s = g_csr[j];
        float w = __expf(lrelu(g_ssrc[s] + sdv) - m) * inv;
        float4 xv = ((const float4*)(x + (size_t)s * F0))[tid];
        acc.x += w * xv.x; acc.y += w * xv.y;
        acc.z += w * xv.z; acc.w += w * xv.w;
    }
    // store half: agg1 only feeds GEMM1's A operand
    __half2 h0 = __floats2half2_rn(acc.x, acc.y);
    __half2 h1v = __floats2half2_rn(acc.z, acc.w);
    __half2* o = (__half2*)(g_agg1h + (size_t)n * F0);
    o[tid * 2 + 0] = h0;
    o[tid * 2 + 1] = h1v;
}

__global__ void k_gat2(const float* __restrict__ b2) {
    int n = blockIdx.x, tid = threadIdx.x;   // 256 threads
    int rs = g_off[n], re = g_off[n + 1];
    float sdv = g_sdst[n];
    __shared__ float red[256];
    float m = -1e30f;
    for (int j = rs + tid; j < re; j += 256)
        m = fmaxf(m, lrelu(g_ssrc[g_csr[j]] + sdv));
    red[tid] = m; __syncthreads();
    for (int s = 128; s > 0; s >>= 1) {
        if (tid < s) red[tid] = fmaxf(red[tid], red[tid + s]);
        __syncthreads();
    }
    m = red[0]; __syncthreads();
    float den = 0.f;
    for (int j = rs + tid; j < re; j += 256)
        den += __expf(lrelu(g_ssrc[g_csr[j]] + sdv) - m);
    red[tid] = den; __syncthreads();
    for (int s = 128; s > 0; s >>= 1) {
        if (tid < s) red[tid] += red[tid + s];
        __syncthreads();
    }
    float inv = 1.0f / red[0];
    float4 acc = make_float4(0.f, 0.f, 0.f, 0.f);
    for (int j = rs; j < re; j++) {
        int s = g_csr[j];
        float w = __expf(lrelu(g_ssrc[s] + sdv) - m) * inv;
        float4 hv = ((const float4*)(g_h2 + (size_t)s * F2))[tid];
        acc.x += w * hv.x; acc.y += w * hv.y;
        acc.z += w * hv.z; acc.w += w * hv.w;
    }
    float4 bv = ((const float4*)b2)[tid];
    acc.x = fmaxf(acc.x + bv.x, 0.f);
    acc.y = fmaxf(acc.y + bv.y, 0.f);
    acc.z = fmaxf(acc.z + bv.z, 0.f);
    acc.w = fmaxf(acc.w + bv.w, 0.f);
    ((float4*)(g_agg2 + (size_t)n * F2))[tid] = acc;
}

// ---------------- layer 3: tiny GEMM then fused gather + log_softmax ----------------
__global__ void k_gemm3(const float* __restrict__ W3) {
    int node = blockIdx.x;
    int warp = threadIdx.x >> 5;   // 0..6
    int lane = threadIdx.x & 31;
    const float* a = g_agg2 + (size_t)node * F2;
    float s = 0.f;
    for (int k = lane; k < F2; k += 32) s += a[k] * W3[k * F3 + warp];
    #pragma unroll
    for (int o = 16; o > 0; o >>= 1) s += __shfl_down_sync(0xffffffff, s, o);
    if (lane == 0) g_h3[node * F3 + warp] = s;
}

__global__ void k_gat3f(const float* __restrict__ b3, float* __restrict__ out) {
    int wg = (blockIdx.x * blockDim.x + threadIdx.x) >> 5;
    if (wg >= NN) return;
    int lane = threadIdx.x & 31;
    int rs = g_off[wg], re = g_off[wg + 1];
    float sdv = g_sdst[wg];
    float m = -1e30f;
    for (int j = rs + lane; j < re; j += 32)
        m = fmaxf(m, lrelu(g_ssrc[g_csr[j]] + sdv));
    #pragma unroll
    for (int o = 16; o > 0; o >>= 1) m = fmaxf(m, __shfl_xor_sync(0xffffffff, m, o));
    float den = 0.f;
    for (int j = rs + lane; j < re; j += 32)
        den += __expf(lrelu(g_ssrc[g_csr[j]] + sdv) - m);
    #pragma unroll
    for (int o = 16; o > 0; o >>= 1) den += __shfl_xor_sync(0xffffffff, den, o);
    float inv = 1.0f / den;
    float acc = 0.f;
    for (int j = rs; j < re; j++) {
        int s = g_csr[j];
        float w = __expf(lrelu(g_ssrc[s] + sdv) - m) * inv;
        if (lane < F3) acc += w * g_h3[s * F3 + lane];
    }
    float z = (lane < F3) ? acc + b3[lane] : -1e30f;
    float mz = z;
    #pragma unroll
    for (int o = 16; o > 0; o >>= 1) mz = fmaxf(mz, __shfl_xor_sync(0xffffffff, mz, o));
    float e = (lane < F3) ? expf(z - mz) : 0.f;
    #pragma unroll
    for (int o = 16; o > 0; o >>= 1) e += __shfl_xor_sync(0xffffffff, e, o);
    float l = mz + logf(e);
    if (lane < F3) out[wg * F3 + lane] = z - l;
}

// ---------------- fp16 mma.sync GEMM, cp.async pipelined ----------------
// C[M,Nc] = A[M,K] @ Bt[Nc,K]^T ; A half [m][k], Bt half [n][k] (pre-transposed).
// BM=128, BN=256, BK=64, 512 threads (16 warps, 4x4). Warp tile 32x64.
// mma m16n8k16 f16 -> 4 ks-steps per k-tile.
// SMEM rows padded to 72 halves (36 words; bank pattern 4g+c injective).
#define SH_STR 72
#define ST_A_B (128 * SH_STR * 2)        // 18432 bytes
#define ST_B_B (256 * SH_STR * 2)        // 36864 bytes
#define ST_BYTES (ST_A_B + ST_B_B)       // 55296 bytes per stage
#define SM_BYTES (2 * ST_BYTES)          // 110592 bytes

__device__ __forceinline__ void g_fill_async(const __half* __restrict__ A,
                                             const __half* __restrict__ Bt,
                                             uint32_t sa_u, uint32_t sb_u,
                                             int row0, int col0, int kt,
                                             int M, int K, int tid) {
    #pragma unroll
    for (int i = 0; i < 2; i++) {          // A: 128 rows x 8 chunks(16B) = 1024 / 512 thr
        int idx = i * 512 + tid;
        int m = idx >> 3, k8 = idx & 7;
        int gr = row0 + m;
        int ok = gr < M;
        const __half* src = A + (size_t)(ok ? gr : row0) * K + kt * 64 + k8 * 8;
        cpa16(sa_u + (uint32_t)(m * SH_STR + k8 * 8) * 2, src, ok ? 16 : 0);
    }
    #pragma unroll
    for (int i = 0; i < 4; i++) {          // B: 256 rows x 8 chunks = 2048 / 512 thr
        int idx = i * 512 + tid;
        int n = idx >> 3, k8 = idx & 7;
        const __half* src = Bt + (size_t)(col0 + n) * K + kt * 64 + k8 * 8;
        cpa16(sb_u + (uint32_t)(n * SH_STR + k8 * 8) * 2, src, 16);
    }
    asm volatile("cp.async.commit_group;" ::: "memory");
}

__global__ void __launch_bounds__(512, 1)
tc_gemm(const __half* __restrict__ A, const __half* __restrict__ Bt, void* __restrict__ Cv,
        int M, int Nc, int K, const float* __restrict__ bias, int doRelu, int outHalf) {
    extern __shared__ __half smh[];
    uint32_t smu = smem_u32(smh);
    int tid = threadIdx.x;
    int lane = tid & 31, wid = tid >> 5;
    int warp_m = wid & 3, warp_n = wid >> 2;   // 4 x 4
    int g = lane >> 2, c = lane & 3;
    int row0 = blockIdx.y * 128, col0 = blockIdx.x * 256;

    const uint32_t A_byte[2] = { 0u, (uint32_t)ST_BYTES };
    const uint32_t B_byte[2] = { (uint32_t)ST_A_B, (uint32_t)(ST_BYTES + ST_A_B) };

    float acc[2][8][4];
    #pragma unroll
    for (int t = 0; t < 2; t++)
        #pragma unroll
        for (int u = 0; u < 8; u++)
            #pragma unroll
            for (int j = 0; j < 4; j++) acc[t][u][j] = 0.f;

    const int KT = K >> 6;
    g_fill_async(A, Bt, smu + A_byte[0], smu + B_byte[0], row0, col0, 0, M, K, tid);

    for (int kt = 0; kt < KT; kt++) {
        int buf = kt & 1;
        if (kt + 1 < KT) {
            g_fill_async(A, Bt, smu + A_byte[buf ^ 1], smu + B_byte[buf ^ 1],
                         row0, col0, kt + 1, M, K, tid);
            asm volatile("cp.async.wait_group 1;" ::: "memory");
        } else {
            asm volatile("cp.async.wait_group 0;" ::: "memory");
        }
        __syncthreads();
        const __half* sa = smh + A_byte[buf] / 2;
        const __half* sb = smh + B_byte[buf] / 2;
        #pragma unroll
        for (int ks = 0; ks < 4; ks++) {
            uint32_t af[2][4];
            #pragma unroll
            for (int t = 0; t < 2; t++) {
                const __half* pa = sa + (warp_m * 32 + t * 16 + g) * SH_STR + ks * 16 + 2 * c;
                af[t][0] = *(const uint32_t*)(pa);
                af[t][1] = *(const uint32_t*)(pa + 8 * SH_STR);
                af[t][2] = *(const uint32_t*)(pa + 8);
                af[t][3] = *(const uint32_t*)(pa + 8 * SH_STR + 8);
            }
            uint32_t bf[8][2];
            #pragma unroll
            for (int u = 0; u < 8; u++) {
                const __half* pb = sb + (warp_n * 64 + u * 8 + g) * SH_STR + ks * 16 + 2 * c;
                bf[u][0] = *(const uint32_t*)(pb);
                bf[u][1] = *(const uint32_t*)(pb + 8);
            }
            #pragma unroll
            for (int t = 0; t < 2; t++)
                #pragma unroll
                for (int u = 0; u < 8; u++)
                    mma16(acc[t][u], af[t], bf[u]);
        }
        __syncthreads();
    }

    // epilogue
    #pragma unroll
    for (int t = 0; t < 2; t++) {
        int r0 = row0 + warp_m * 32 + t * 16 + g;
        #pragma unroll
        for (int u = 0; u < 8; u++) {
            int cc = col0 + warp_n * 64 + u * 8 + 2 * c;
            float2 v0 = make_float2(acc[t][u][0], acc[t][u][1]);
            float2 v1 = make_float2(acc[t][u][2], acc[t][u][3]);
            if (bias) {
                float b0v = bias[cc], b1v = bias[cc + 1];
                v0.x += b0v; v0.y += b1v;
                v1.x += b0v; v1.y += b1v;
            }
            if (doRelu) {
                v0.x = fmaxf(v0.x, 0.f); v0.y = fmaxf(v0.y, 0.f);
                v1.x = fmaxf(v1.x, 0.f); v1.y = fmaxf(v1.y, 0.f);
            }
            if (outHalf) {
                __half* C = (__half*)Cv;
                if (r0 < M)
                    *(__half2*)(C + (size_t)r0 * Nc + cc) = __floats2half2_rn(v0.x, v0.y);
                if (r0 + 8 < M)
                    *(__half2*)(C + (size_t)(r0 + 8) * Nc + cc) = __floats2half2_rn(v1.x, v1.y);
            } else {
                float* C = (float*)Cv;
                if (r0 < M)     *(float2*)(C + (size_t)r0 * Nc + cc) = v0;
                if (r0 + 8 < M) *(float2*)(C + (size_t)(r0 + 8) * Nc + cc) = v1;
            }
        }
    }
}

// ---------------- launch ----------------
extern "C" void kernel_launch(void* const* d_in, const int* in_sizes, int n_in,
                              void* d_out, int out_size) {
    const float* x   = (const float*)d_in[0];
    const int*   ei  = (const int*)d_in[1];
    const float* W1  = (const float*)d_in[2];
    const float* as1 = (const float*)d_in[3];
    const float* ad1 = (const float*)d_in[4];
    const float* b1  = (const float*)d_in[5];
    const float* W2  = (const float*)d_in[6];
    const float* as2 = (const float*)d_in[7];
    const float* ad2 = (const float*)d_in[8];
    const float* b2  = (const float*)d_in[9];
    const float* W3  = (const float*)d_in[10];
    const float* as3 = (const float*)d_in[11];
    const float* ad3 = (const float*)d_in[12];
    const float* b3  = (const float*)d_in[13];
    float* out = (float*)d_out;

    void *p_agg1h, *p_agg2, *p_h1h, *p_h2, *p_h3, *p_v1s, *p_v1d, *p_w1t, *p_w2t;
    cudaGetSymbolAddress(&p_agg1h, g_agg1h);
    cudaGetSymbolAddress(&p_agg2, g_agg2);
    cudaGetSymbolAddress(&p_h1h, g_h1h);
    cudaGetSymbolAddress(&p_h2, g_h2);
    cudaGetSymbolAddress(&p_h3, g_h3);
    cudaGetSymbolAddress(&p_v1s, g_v1s);
    cudaGetSymbolAddress(&p_v1d, g_v1d);
    cudaGetSymbolAddress(&p_w1t, g_w1t);
    cudaGetSymbolAddress(&p_w2t, g_w2t);

    cudaFuncSetAttribute(tc_gemm, cudaFuncAttributeMaxDynamicSharedMemorySize, SM_BYTES);

    const int EB = (EE + 255) / 256;
    const int MB = (NN + 127) / 128;

    // ---- weight transpose + fp16 convert (once, independent) ----
    k_transpose_h<<<dim3(F1 / 32, F0 / 32), dim3(32, 8)>>>(W1, (__half*)p_w1t, F0, F1);
    k_transpose_h<<<dim3(F2 / 32, F1 / 32), dim3(32, 8)>>>(W2, (__half*)p_w2t, F1, F2);

    // ---- CSR build (reused by all 3 layers) ----
    k_zerodeg<<<(NN + 255) / 256, 256>>>();
    k_deg<<<EB, 256>>>(ei);
    k_scan<<<1, 1024>>>();
    k_fill<<<EB, 256>>>(ei);

    // ---- Layer 1: scores on x, gather in x-space (512, ->half), then GEMM ----
    k_v1<<<F0, 256>>>(W1, as1, ad1);
    k_scores<<<NN, 128>>>(x, (const float*)p_v1s, (const float*)p_v1d, F0);
    k_gat1<<<NN, 128>>>(x);
    {
        dim3 grd(F1 / 256, MB);
        tc_gemm<<<grd, 512, SM_BYTES>>>((const __half*)p_agg1h, (const __half*)p_w1t,
                                        p_h1h, NN, F1, F0, b1, 1, 1);
    }

    // ---- Layer 2: GEMM (4096->1024, fp32 out), scores, gather (+bias+relu) ----
    {
        dim3 grd(F2 / 256, MB);
        tc_gemm<<<grd, 512, SM_BYTES>>>((const __half*)p_h1h, (const __half*)p_w2t,
                                        p_h2, NN, F2, F1, nullptr, 0, 0);
    }
    k_scores<<<NN, 128>>>((const float*)p_h2, as2, ad2, F2);
    k_gat2<<<NN, 256>>>(b2);

    // ---- Layer 3: tiny GEMM (1024->7), scores, fused gather+log_softmax ----
    k_gemm3<<<NN, 224>>>(W3);
    k_scores<<<NN, 128>>>((const float*)p_h3, as3, ad3, F3);
    k_gat3f<<<(NN * 32 + 255) / 256, 256>>>(b3, out);
}

// round 10
// speedup vs baseline: 9.1155x; 1.0735x over previous
#include <cuda_runtime.h>
#include <cuda_fp16.h>
#include <math.h>
#include <stdint.h>

#define NN 10000
#define E0 80000
#define EE 90000
#define F0 512
#define F1 4096
#define F2 1024
#define F3 7
#define NSLOPE 0.2f

// ---------------- scratch (static device globals; no allocation) ----------------
__device__ __half g_agg1h[(size_t)NN * F0];     // half agg (A of GEMM1)
__device__ __half g_h1h[(size_t)NN * F1];       // half h1 (A of GEMM2)
__device__ float  g_h2[(size_t)NN * F2];
__device__ float  g_agg2[(size_t)NN * F2];
__device__ float  g_h3[NN * F3];
__device__ float  g_ssrc[NN], g_sdst[NN];
__device__ float  g_v1s[F0], g_v1d[F0];
__device__ __half g_w1t[(size_t)F1 * F0];       // W1^T half [N][K]
__device__ __half g_w2t[(size_t)F2 * F1];       // W2^T half [N][K]
// CSR by destination
__device__ int g_deg[NN];
__device__ int g_cursor[NN];
__device__ int g_off[NN + 1];
__device__ int g_csr[EE];

__device__ __forceinline__ void edge_sd(const int* __restrict__ ei, int e, int& s, int& d) {
    if (e < E0) { s = ei[e]; d = ei[E0 + e]; }
    else        { s = e - E0; d = e - E0; }
}
__device__ __forceinline__ uint32_t smem_u32(const void* p) {
    uint32_t a;
    asm("{ .reg .u64 t; cvta.to.shared.u64 t, %1; cvt.u32.u64 %0, t; }" : "=r"(a) : "l"(p));
    return a;
}
__device__ __forceinline__ void cpa16(uint32_t dst, const void* src, int sz) {
    asm volatile("cp.async.cg.shared.global [%0], [%1], 16, %2;"
                 :: "r"(dst), "l"(src), "r"(sz));
}
// fp16 MMA m16n8k16, fp32 accumulate
__device__ __forceinline__ void mma16(float* c, const uint32_t* a, const uint32_t* b) {
    asm volatile(
        "mma.sync.aligned.m16n8k16.row.col.f32.f16.f16.f32 "
        "{%0,%1,%2,%3}, {%4,%5,%6,%7}, {%8,%9}, {%0,%1,%2,%3};"
        : "+f"(c[0]), "+f"(c[1]), "+f"(c[2]), "+f"(c[3])
        : "r"(a[0]), "r"(a[1]), "r"(a[2]), "r"(a[3]), "r"(b[0]), "r"(b[1]));
}
__device__ __forceinline__ void ldm4(uint32_t* r, uint32_t addr) {
    asm volatile("ldmatrix.sync.aligned.m8n8.x4.shared.b16 {%0,%1,%2,%3}, [%4];"
                 : "=r"(r[0]), "=r"(r[1]), "=r"(r[2]), "=r"(r[3]) : "r"(addr));
}
__device__ __forceinline__ float lrelu(float v) { return (v > 0.f) ? v : NSLOPE * v; }

// ---------------- weight transpose + fp16 convert: out[n][k] = half(in[k][n]) ----------------
__global__ void k_transpose_h(const float* __restrict__ in, __half* __restrict__ out,
                              int K, int N) {
    __shared__ __half tile[32][34];
    int n0 = blockIdx.x * 32, k0 = blockIdx.y * 32;
    int tx = threadIdx.x, ty = threadIdx.y;   // 32 x 8
    #pragma unroll
    for (int i = 0; i < 4; i++) {
        int k = k0 + ty + i * 8;
        tile[ty + i * 8][tx] = __float2half_rn(in[(size_t)k * N + n0 + tx]);
    }
    __syncthreads();
    #pragma unroll
    for (int i = 0; i < 4; i++) {
        int n = n0 + ty + i * 8;
        out[(size_t)n * K + k0 + tx] = tile[tx][ty + i * 8];
    }
}

// ---------------- CSR build ----------------
__global__ void k_zerodeg() {
    int i = blockIdx.x * blockDim.x + threadIdx.x;
    if (i < NN) g_deg[i] = 0;
}
__global__ void k_deg(const int* __restrict__ ei) {
    int e = blockIdx.x * blockDim.x + threadIdx.x;
    if (e >= EE) return;
    int s, d; edge_sd(ei, e, s, d);
    atomicAdd(&g_deg[d], 1);
}
__global__ void k_scan() {   // single block, 1024 threads, chunk=10
    __shared__ int sh[1024];
    int tid = threadIdx.x;
    int base = tid * 10;
    int cnt[10]; int local = 0;
    #pragma unroll
    for (int i = 0; i < 10; i++) {
        int idx = base + i;
        int c = (idx < NN) ? g_deg[idx] : 0;
        cnt[i] = local; local += c;
    }
    sh[tid] = local;
    __syncthreads();
    for (int off = 1; off < 1024; off <<= 1) {
        int v = (tid >= off) ? sh[tid - off] : 0;
        __syncthreads();
        sh[tid] += v;
        __syncthreads();
    }
    int start = sh[tid] - local;
    #pragma unroll
    for (int i = 0; i < 10; i++) {
        int idx = base + i;
        if (idx < NN) { g_off[idx] = start + cnt[i]; g_cursor[idx] = 0; }
    }
    if (tid == 1023) g_off[NN] = sh[1023];
}
__global__ void k_fill(const int* __restrict__ ei) {
    int e = blockIdx.x * blockDim.x + threadIdx.x;
    if (e >= EE) return;
    int s, d; edge_sd(ei, e, s, d);
    int p = atomicAdd(&g_cursor[d], 1);
    g_csr[g_off[d] + p] = s;
}

// ---------------- attention-vector & node-score kernels ----------------
__global__ void k_v1(const float* __restrict__ W1, const float* __restrict__ as,
                     const float* __restrict__ ad) {
    int r = blockIdx.x;
    int tid = threadIdx.x;
    float ss = 0.f, sd = 0.f;
    const float* wrow = W1 + (size_t)r * F1;
    for (int j = tid; j < F1; j += 256) {
        float w = wrow[j];
        ss += w * as[j];
        sd += w * ad[j];
    }
    __shared__ float s1[256], s2[256];
    s1[tid] = ss; s2[tid] = sd;
    __syncthreads();
    for (int s = 128; s > 0; s >>= 1) {
        if (tid < s) { s1[tid] += s1[tid + s]; s2[tid] += s2[tid + s]; }
        __syncthreads();
    }
    if (tid == 0) { g_v1s[r] = s1[0]; g_v1d[r] = s2[0]; }
}

__global__ void k_scores(const float* __restrict__ X, const float* __restrict__ vs,
                         const float* __restrict__ vd, int F) {
    int node = blockIdx.x;
    int tid = threadIdx.x;      // 128
    const float* xr = X + (size_t)node * F;
    float ss = 0.f, sd = 0.f;
    for (int j = tid; j < F; j += 128) {
        float x = xr[j];
        ss += x * vs[j];
        sd += x * vd[j];
    }
    __shared__ float s1[128], s2[128];
    s1[tid] = ss; s2[tid] = sd;
    __syncthreads();
    for (int s = 64; s > 0; s >>= 1) {
        if (tid < s) { s1[tid] += s1[tid + s]; s2[tid] += s2[tid + s]; }
        __syncthreads();
    }
    if (tid == 0) { g_ssrc[node] = s1[0]; g_sdst[node] = s2[0]; }
}

// ---------------- gather aggregation (softmax fused, no atomics) ----------------
__global__ void k_gat1(const float* __restrict__ x) {
    int n = blockIdx.x, tid = threadIdx.x;   // 128 threads
    int rs = g_off[n], re = g_off[n + 1];
    float sdv = g_sdst[n];
    __shared__ float red[128];
    float m = -1e30f;
    for (int j = rs + tid; j < re; j += 128)
        m = fmaxf(m, lrelu(g_ssrc[g_csr[j]] + sdv));
    red[tid] = m; __syncthreads();
    for (int s = 64; s > 0; s >>= 1) {
        if (tid < s) red[tid] = fmaxf(red[tid], red[tid + s]);
        __syncthreads();
    }
    m = red[0]; __syncthreads();
    float den = 0.f;
    for (int j = rs + tid; j < re; j += 128)
        den += __expf(lrelu(g_ssrc[g_csr[j]] + sdv) - m);
    red[tid] = den; __syncthreads();
    for (int s = 64; s > 0; s >>= 1) {
        if (tid < s) red[tid] += red[tid + s];
        __syncthreads();
    }
    float inv = 1.0f / red[0];
    float4 acc = make_float4(0.f, 0.f, 0.f, 0.f);
    for (int j = rs; j < re; j++) {
        int s = g_csr[j];
        float w = __expf(lrelu(g_ssrc[s] + sdv) - m) * inv;
        float4 xv = ((const float4*)(x + (size_t)s * F0))[tid];
        acc.x += w * xv.x; acc.y += w * xv.y;
        acc.z += w * xv.z; acc.w += w * xv.w;
    }
    __half2 h0 = __floats2half2_rn(acc.x, acc.y);
    __half2 h1v = __floats2half2_rn(acc.z, acc.w);
    __half2* o = (__half2*)(g_agg1h + (size_t)n * F0);
    o[tid * 2 + 0] = h0;
    o[tid * 2 + 1] = h1v;
}

__global__ void k_gat2(const float* __restrict__ b2) {
    int n = blockIdx.x, tid = threadIdx.x;   // 256 threads
    int rs = g_off[n], re = g_off[n + 1];
    float sdv = g_sdst[n];
    __shared__ float red[256];
    float m = -1e30f;
    for (int j = rs + tid; j < re; j += 256)
        m = fmaxf(m, lrelu(g_ssrc[g_csr[j]] + sdv));
    red[tid] = m; __syncthreads();
    for (int s = 128; s > 0; s >>= 1) {
        if (tid < s) red[tid] = fmaxf(red[tid], red[tid + s]);
        __syncthreads();
    }
    m = red[0]; __syncthreads();
    float den = 0.f;
    for (int j = rs + tid; j < re; j += 256)
        den += __expf(lrelu(g_ssrc[g_csr[j]] + sdv) - m);
    red[tid] = den; __syncthreads();
    for (int s = 128; s > 0; s >>= 1) {
        if (tid < s) red[tid] += red[tid + s];
        __syncthreads();
    }
    float inv = 1.0f / red[0];
    float4 acc = make_float4(0.f, 0.f, 0.f, 0.f);
    for (int j = rs; j < re; j++) {
        int s = g_csr[j];
        float w = __expf(lrelu(g_ssrc[s] + sdv) - m) * inv;
        float4 hv = ((const float4*)(g_h2 + (size_t)s * F2))[tid];
        acc.x += w * hv.x; acc.y += w * hv.y;
        acc.z += w * hv.z; acc.w += w * hv.w;
    }
    float4 bv = ((const float4*)b2)[tid];
    acc.x = fmaxf(acc.x + bv.x, 0.f);
    acc.y = fmaxf(acc.y + bv.y, 0.f);
    acc.z = fmaxf(acc.z + bv.z, 0.f);
    acc.w = fmaxf(acc.w + bv.w, 0.f);
    ((float4*)(g_agg2 + (size_t)n * F2))[tid] = acc;
}

// ---------------- layer 3: tiny GEMM then fused gather + log_softmax ----------------
__global__ void k_gemm3(const float* __restrict__ W3) {
    int node = blockIdx.x;
    int warp = threadIdx.x >> 5;   // 0..6
    int lane = threadIdx.x & 31;
    const float* a = g_agg2 + (size_t)node * F2;
    float s = 0.f;
    for (int k = lane; k < F2; k += 32) s += a[k] * W3[k * F3 + warp];
    #pragma unroll
    for (int o = 16; o > 0; o >>= 1) s += __shfl_down_sync(0xffffffff, s, o);
    if (lane == 0) g_h3[node * F3 + warp] = s;
}

__global__ void k_gat3f(const float* __restrict__ b3, float* __restrict__ out) {
    int wg = (blockIdx.x * blockDim.x + threadIdx.x) >> 5;
    if (wg >= NN) return;
    int lane = threadIdx.x & 31;
    int rs = g_off[wg], re = g_off[wg + 1];
    float sdv = g_sdst[wg];
    float m = -1e30f;
    for (int j = rs + lane; j < re; j += 32)
        m = fmaxf(m, lrelu(g_ssrc[g_csr[j]] + sdv));
    #pragma unroll
    for (int o = 16; o > 0; o >>= 1) m = fmaxf(m, __shfl_xor_sync(0xffffffff, m, o));
    float den = 0.f;
    for (int j = rs + lane; j < re; j += 32)
        den += __expf(lrelu(g_ssrc[g_csr[j]] + sdv) - m);
    #pragma unroll
    for (int o = 16; o > 0; o >>= 1) den += __shfl_xor_sync(0xffffffff, den, o);
    float inv = 1.0f / den;
    float acc = 0.f;
    for (int j = rs; j < re; j++) {
        int s = g_csr[j];
        float w = __expf(lrelu(g_ssrc[s] + sdv) - m) * inv;
        if (lane < F3) acc += w * g_h3[s * F3 + lane];
    }
    float z = (lane < F3) ? acc + b3[lane] : -1e30f;
    float mz = z;
    #pragma unroll
    for (int o = 16; o > 0; o >>= 1) mz = fmaxf(mz, __shfl_xor_sync(0xffffffff, mz, o));
    float e = (lane < F3) ? expf(z - mz) : 0.f;
    #pragma unroll
    for (int o = 16; o > 0; o >>= 1) e += __shfl_xor_sync(0xffffffff, e, o);
    float l = mz + logf(e);
    if (lane < F3) out[wg * F3 + lane] = z - l;
}

// ---------------- fp16 mma.sync GEMM, ldmatrix + 3-stage cp.async ----------------
// C[M,Nc] = A[M,K] @ Bt[Nc,K]^T ; A half [m][k], Bt half [n][k] (pre-transposed).
// BM=128, BN=256, BK=64, 512 threads (16 warps, 4x4). Warp tile 32x64.
// mma m16n8k16 f16 -> 4 ks-steps per k-tile; fragments via ldmatrix.x4.
// SMEM rows padded to 72 halves = 144 B (9x16B -> 8 ldmatrix row addrs hit distinct banks).
#define SH_STR 72
#define ST_A_B (128 * SH_STR * 2)        // 18432 bytes
#define ST_B_B (256 * SH_STR * 2)        // 36864 bytes
#define ST_BYTES (ST_A_B + ST_B_B)       // 55296 bytes per stage
#define NSTAGE 3
#define SM_BYTES (NSTAGE * ST_BYTES)     // 165888 bytes

__device__ __forceinline__ void g_fill_async(const __half* __restrict__ A,
                                             const __half* __restrict__ Bt,
                                             uint32_t sa_u, uint32_t sb_u,
                                             int row0, int col0, int kt,
                                             int M, int K, int tid) {
    #pragma unroll
    for (int i = 0; i < 2; i++) {          // A: 128 rows x 8 chunks(16B) = 1024 / 512 thr
        int idx = i * 512 + tid;
        int m = idx >> 3, k8 = idx & 7;
        int gr = row0 + m;
        int ok = gr < M;
        const __half* src = A + (size_t)(ok ? gr : row0) * K + kt * 64 + k8 * 8;
        cpa16(sa_u + (uint32_t)(m * SH_STR + k8 * 8) * 2, src, ok ? 16 : 0);
    }
    #pragma unroll
    for (int i = 0; i < 4; i++) {          // B: 256 rows x 8 chunks = 2048 / 512 thr
        int idx = i * 512 + tid;
        int n = idx >> 3, k8 = idx & 7;
        const __half* src = Bt + (size_t)(col0 + n) * K + kt * 64 + k8 * 8;
        cpa16(sb_u + (uint32_t)(n * SH_STR + k8 * 8) * 2, src, 16);
    }
    asm volatile("cp.async.commit_group;" ::: "memory");
}

__global__ void __launch_bounds__(512, 1)
tc_gemm(const __half* __restrict__ A, const __half* __restrict__ Bt, void* __restrict__ Cv,
        int M, int Nc, int K, const float* __restrict__ bias, int doRelu, int outHalf) {
    extern __shared__ __half smh[];
    uint32_t smu = smem_u32(smh);
    int tid = threadIdx.x;
    int lane = tid & 31, wid = tid >> 5;
    int warp_m = wid & 3, warp_n = wid >> 2;   // 4 x 4
    int g = lane >> 2, c = lane & 3;
    int lr = lane & 7, lm = lane >> 3;         // ldmatrix row / matrix idx
    int row0 = blockIdx.y * 128, col0 = blockIdx.x * 256;

    // per-lane ldmatrix byte offsets (within a stage)
    // A x4: {M0 rows0-7/k0-7, M1 rows8-15/k0-7, M2 rows0-7/k8-15, M3 rows8-15/k8-15}
    uint32_t a_loff = ((uint32_t)(warp_m * 32 + lr + (lm & 1) * 8) * SH_STR
                       + ((lm >> 1) & 1) * 8) * 2;
    // B x4 (pair of n8 tiles): {b0(u), b1(u), b0(u+1), b1(u+1)}
    uint32_t b_loff = (uint32_t)ST_A_B
                      + ((uint32_t)(warp_n * 64 + lr + ((lm >> 1) & 1) * 8) * SH_STR
                         + (lm & 1) * 8) * 2;

    float acc[2][8][4];
    #pragma unroll
    for (int t = 0; t < 2; t++)
        #pragma unroll
        for (int u = 0; u < 8; u++)
            #pragma unroll
            for (int j = 0; j < 4; j++) acc[t][u][j] = 0.f;

    const int KT = K >> 6;
    g_fill_async(A, Bt, smu, smu + ST_A_B, row0, col0, 0, M, K, tid);
    if (KT > 1)
        g_fill_async(A, Bt, smu + ST_BYTES, smu + ST_BYTES + ST_A_B, row0, col0, 1, M, K, tid);

    for (int kt = 0; kt < KT; kt++) {
        int buf = kt % NSTAGE;
        if (kt + 2 < KT) {
            int nb = (kt + 2) % NSTAGE;
            g_fill_async(A, Bt, smu + nb * ST_BYTES, smu + nb * ST_BYTES + ST_A_B,
                         row0, col0, kt + 2, M, K, tid);
            asm volatile("cp.async.wait_group 2;" ::: "memory");
        } else if (kt + 1 < KT) {
            asm volatile("cp.async.wait_group 1;" ::: "memory");
        } else {
            asm volatile("cp.async.wait_group 0;" ::: "memory");
        }
        __syncthreads();
        uint32_t st = smu + buf * ST_BYTES;
        #pragma unroll
        for (int ks = 0; ks < 4; ks++) {
            uint32_t af[2][4];
            #pragma unroll
            for (int t = 0; t < 2; t++)
                ldm4(af[t], st + a_loff + (uint32_t)(t * 16 * SH_STR * 2) + ks * 32);
            uint32_t bf[8][2];
            #pragma unroll
            for (int p = 0; p < 4; p++) {
                uint32_t r4[4];
                ldm4(r4, st + b_loff + (uint32_t)(p * 16 * SH_STR * 2) + ks * 32);
                bf[p * 2][0] = r4[0];     bf[p * 2][1] = r4[1];
                bf[p * 2 + 1][0] = r4[2]; bf[p * 2 + 1][1] = r4[3];
            }
            #pragma unroll
            for (int t = 0; t < 2; t++)
                #pragma unroll
                for (int u = 0; u < 8; u++)
                    mma16(acc[t][u], af[t], bf[u]);
        }
        __syncthreads();
    }

    // epilogue
    #pragma unroll
    for (int t = 0; t < 2; t++) {
        int r0 = row0 + warp_m * 32 + t * 16 + g;
        #pragma unroll
        for (int u = 0; u < 8; u++) {
            int cc = col0 + warp_n * 64 + u * 8 + 2 * c;
            float2 v0 = make_float2(acc[t][u][0], acc[t][u][1]);
            float2 v1 = make_float2(acc[t][u][2], acc[t][u][3]);
            if (bias) {
                float b0v = bias[cc], b1v = bias[cc + 1];
                v0.x += b0v; v0.y += b1v;
                v1.x += b0v; v1.y += b1v;
            }
            if (doRelu) {
                v0.x = fmaxf(v0.x, 0.f); v0.y = fmaxf(v0.y, 0.f);
                v1.x = fmaxf(v1.x, 0.f); v1.y = fmaxf(v1.y, 0.f);
            }
            if (outHalf) {
                __half* C = (__half*)Cv;
                if (r0 < M)
                    *(__half2*)(C + (size_t)r0 * Nc + cc) = __floats2half2_rn(v0.x, v0.y);
                if (r0 + 8 < M)
                    *(__half2*)(C + (size_t)(r0 + 8) * Nc + cc) = __floats2half2_rn(v1.x, v1.y);
            } else {
                float* C = (float*)Cv;
                if (r0 < M)     *(float2*)(C + (size_t)r0 * Nc + cc) = v0;
                if (r0 + 8 < M) *(float2*)(C + (size_t)(r0 + 8) * Nc + cc) = v1;
            }
        }
    }
}

// ---------------- launch ----------------
extern "C" void kernel_launch(void* const* d_in, const int* in_sizes, int n_in,
                              void* d_out, int out_size) {
    const float* x   = (const float*)d_in[0];
    const int*   ei  = (const int*)d_in[1];
    const float* W1  = (const float*)d_in[2];
    const float* as1 = (const float*)d_in[3];
    const float* ad1 = (const float*)d_in[4];
    const float* b1  = (const float*)d_in[5];
    const float* W2  = (const float*)d_in[6];
    const float* as2 = (const float*)d_in[7];
    const float* ad2 = (const float*)d_in[8];
    const float* b2  = (const float*)d_in[9];
    const float* W3  = (const float*)d_in[10];
    const float* as3 = (const float*)d_in[11];
    const float* ad3 = (const float*)d_in[12];
    const float* b3  = (const float*)d_in[13];
    float* out = (float*)d_out;

    void *p_agg1h, *p_agg2, *p_h1h, *p_h2, *p_h3, *p_v1s, *p_v1d, *p_w1t, *p_w2t;
    cudaGetSymbolAddress(&p_agg1h, g_agg1h);
    cudaGetSymbolAddress(&p_agg2, g_agg2);
    cudaGetSymbolAddress(&p_h1h, g_h1h);
    cudaGetSymbolAddress(&p_h2, g_h2);
    cudaGetSymbolAddress(&p_h3, g_h3);
    cudaGetSymbolAddress(&p_v1s, g_v1s);
    cudaGetSymbolAddress(&p_v1d, g_v1d);
    cudaGetSymbolAddress(&p_w1t, g_w1t);
    cudaGetSymbolAddress(&p_w2t, g_w2t);

    cudaFuncSetAttribute(tc_gemm, cudaFuncAttributeMaxDynamicSharedMemorySize, SM_BYTES);

    const int EB = (EE + 255) / 256;
    const int MB = (NN + 127) / 128;

    // ---- weight transpose + fp16 convert (once, independent) ----
    k_transpose_h<<<dim3(F1 / 32, F0 / 32), dim3(32, 8)>>>(W1, (__half*)p_w1t, F0, F1);
    k_transpose_h<<<dim3(F2 / 32, F1 / 32), dim3(32, 8)>>>(W2, (__half*)p_w2t, F1, F2);

    // ---- CSR build (reused by all 3 layers) ----
    k_zerodeg<<<(NN + 255) / 256, 256>>>();
    k_deg<<<EB, 256>>>(ei);
    k_scan<<<1, 1024>>>();
    k_fill<<<EB, 256>>>(ei);

    // ---- Layer 1: scores on x, gather in x-space (512, ->half), then GEMM ----
    k_v1<<<F0, 256>>>(W1, as1, ad1);
    k_scores<<<NN, 128>>>(x, (const float*)p_v1s, (const float*)p_v1d, F0);
    k_gat1<<<NN, 128>>>(x);
    {
        dim3 grd(F1 / 256, MB);
        tc_gemm<<<grd, 512, SM_BYTES>>>((const __half*)p_agg1h, (const __half*)p_w1t,
                                        p_h1h, NN, F1, F0, b1, 1, 1);
    }

    // ---- Layer 2: GEMM (4096->1024, fp32 out), scores, gather (+bias+relu) ----
    {
        dim3 grd(F2 / 256, MB);
        tc_gemm<<<grd, 512, SM_BYTES>>>((const __half*)p_h1h, (const __half*)p_w2t,
                                        p_h2, NN, F2, F1, nullptr, 0, 0);
    }
    k_scores<<<NN, 128>>>((const float*)p_h2, as2, ad2, F2);
    k_gat2<<<NN, 256>>>(b2);

    // ---- Layer 3: tiny GEMM (1024->7), scores, fused gather+log_softmax ----
    k_gemm3<<<NN, 224>>>(W3);
    k_scores<<<NN, 128>>>((const float*)p_h3, as3, ad3, F3);
    k_gat3f<<<(NN * 32 + 255) / 256, 256>>>(b3, out);
}